// round 13
// baseline (speedup 1.0000x reference)
#include <cuda_runtime.h>
#include <cuda_fp16.h>
#include <cstdint>
#include <math.h>

// ---------------------------------------------------------------------------
// LegalMultiHeadAttention — Round 13: R12 structure (64-K stages, 3-stage
// cp.async, frag double-buffer, chunk-XOR swizzle) with ldmatrix.x4 fragment
// loads (128 LDS -> 32 LDSM per warp-stage). Single-variable retest of LDSM.
//   B=2, S=4096, D_MODEL=1024, H=4, D_K=256.
// ---------------------------------------------------------------------------

#define SEQ    4096
#define DK     256
#define DM     1024
#define NH     4
#define NB     2
#define BS_TOT (NB*SEQ)          // 8192
#define NROWS  (NH*NB*SEQ)       // 32768

__device__ __half g_qin[(size_t)BS_TOT*DM];
__device__ __half g_kin[(size_t)BS_TOT*DM];
__device__ __half g_vin[(size_t)BS_TOT*DM];
__device__ __half g_Qh [(size_t)NH*BS_TOT*DK];
__device__ __half g_Kh [(size_t)NH*BS_TOT*DK];
__device__ __half g_VTh[(size_t)NH*BS_TOT*DK];    // [z][DK][SEQ], written by proj
__device__ __half g_HOh[(size_t)BS_TOT*DM];
__device__ __half g_WTh[(size_t)3*NH*DK*DM];
__device__ __half g_WoTh[(size_t)DM*DM];
__device__ __half g_Eh [(size_t)NH*NB*SEQ*SEQ];   // unnormalized exp
__device__ float  g_psum[(size_t)NROWS*64];
__device__ float  g_invsum[NROWS];
__device__ float  g_attn_fallback[(size_t)NH*NB*SEQ*SEQ];

__device__ __forceinline__ uint32_t smem_u32(const void* p) {
    uint32_t a;
    asm("{ .reg .u64 t; cvta.to.shared.u64 t, %1; cvt.u32.u64 %0, t; }"
        : "=r"(a) : "l"(p));
    return a;
}
__device__ __forceinline__ void mma_f16(float& c0, float& c1, float& c2, float& c3,
                                        uint32_t a0, uint32_t a1, uint32_t a2, uint32_t a3,
                                        uint32_t b0, uint32_t b1) {
    asm volatile(
        "mma.sync.aligned.m16n8k16.row.col.f32.f16.f16.f32 "
        "{%0,%1,%2,%3}, {%4,%5,%6,%7}, {%8,%9}, {%0,%1,%2,%3};"
        : "+f"(c0), "+f"(c1), "+f"(c2), "+f"(c3)
        : "r"(a0), "r"(a1), "r"(a2), "r"(a3), "r"(b0), "r"(b1));
}
__device__ __forceinline__ void ldsm4(uint32_t& r0, uint32_t& r1, uint32_t& r2, uint32_t& r3,
                                      uint32_t addr) {
    asm volatile("ldmatrix.sync.aligned.m8n8.x4.shared.b16 {%0,%1,%2,%3}, [%4];"
                 : "=r"(r0), "=r"(r1), "=r"(r2), "=r"(r3) : "r"(addr));
}
__device__ __forceinline__ void cp16(uint32_t dst, const void* src) {
    asm volatile("cp.async.cg.shared.global [%0], [%1], 16;" :: "r"(dst), "l"(src));
}

#define NSTAGE 3
#define BUF_WORDS 12288                      // 384 rows * 32 words (64 fp16)
#define SMEM_BYTES (NSTAGE*BUF_WORDS*4)      // 147456

// ---------------------------------------------------------------------------
// fp16 GEMM NT: C[m,n] = alpha*sum_k A[m,k]*B[n,k] (+bias[n]).
// 256 threads = 8 warps (WGM x WGN), warp tile 64x64, K staged 64/stage.
// smem row = 32 words (64 halves); 16B chunk c stored at c ^ (row&7).
// Fragments via ldmatrix.x4 (swizzle verified conflict-free per 8-lane phase).
// MODE 0 plain | 1 scores (exp+psum) | 2 av (attn writeback + invrow scale)
//      | 3 transposed fp16 store C[n][m] (ldc = M-stride) for V^T.
// K must be a multiple of 64.
// ---------------------------------------------------------------------------
template<int WGM, int WGN, bool HASBIAS, bool OUTHALF, int MODE>
__device__ __forceinline__ void gemm_h(const __half* __restrict__ A, int lda,
                                       const __half* __restrict__ B, int ldb,
                                       void* __restrict__ Cv, int ldc,
                                       int K, float alpha, const float* __restrict__ bias,
                                       float* __restrict__ aux,
                                       const float* __restrict__ invrow)
{
    extern __shared__ uint32_t smem[];
    const uint32_t sbase = smem_u32(smem);

    const int tid  = threadIdx.x;           // 256
    const int wid  = tid >> 5;
    const int lane = tid & 31;
    const int grp  = lane >> 2;
    const int tg   = lane & 3;
    const int wm   = (wid / WGN) * 64;
    const int wn   = (wid % WGN) * 64;
    const int lrow = lane & 15;              // ldmatrix source row (within 16)
    const int lkh  = lane >> 4;              // 0: low k-chunk, 1: high k-chunk

    const long bm = (long)blockIdx.y * (WGM * 64);
    const long bn = (long)blockIdx.x * (WGN * 64);
    A += bm * (long)lda;
    B += bn * (long)ldb;

    const int sm8 = tid >> 3;                // 0..31 (row within 32-row pass)
    const int skc = tid & 7;                 // 16B chunk 0..7
    const int w4  = (skc ^ (sm8 & 7)) * 4;   // swizzled chunk word offset

    float invs[2 * WGM];
    if (MODE == 2) {
#pragma unroll
        for (int c = 0; c < 2 * WGM; c++)
            invs[c] = invrow[bm + sm8 + c * 32];
    }

    float acc[4][8][4];
#pragma unroll
    for (int i = 0; i < 4; i++)
#pragma unroll
        for (int j = 0; j < 8; j++)
#pragma unroll
            for (int r = 0; r < 4; r++) acc[i][j][r] = 0.0f;

    const int NIT = K >> 6;
    const int AWORDS = WGM * 64 * 32;

    auto stage_copy = [&](int stage, int buf) {
        const uint32_t db = sbase + (uint32_t)buf * (BUF_WORDS * 4);
        const __half* Ak = A + stage * 64 + skc * 8;
        const __half* Bk = B + stage * 64 + skc * 8;
#pragma unroll
        for (int c = 0; c < 2 * WGM; c++) {
            const int r = sm8 + c * 32;
            cp16(db + (uint32_t)(r * 32 + w4) * 4, Ak + (long)r * lda);
        }
        const uint32_t dbB = db + (uint32_t)AWORDS * 4;
#pragma unroll
        for (int c = 0; c < 2 * WGN; c++) {
            const int r = sm8 + c * 32;
            cp16(dbB + (uint32_t)(r * 32 + w4) * 4, Bk + (long)r * ldb);
        }
        asm volatile("cp.async.commit_group;" ::: "memory");
    };

    stage_copy(0, 0);
    stage_copy(1, 1);

    int cbuf = 0;
#pragma unroll 1
    for (int it = 0; it < NIT; it++) {
        asm volatile("cp.async.wait_group %0;" :: "n"(NSTAGE - 2) : "memory");
        __syncthreads();
        if (it + 2 < NIT) {
            int nb = cbuf + 2; if (nb >= NSTAGE) nb -= NSTAGE;
            stage_copy(it + 2, nb);
        }

        const uint32_t* sA = smem + cbuf * BUF_WORDS;
        const uint32_t sAaddr = sbase + (uint32_t)cbuf * (BUF_WORDS * 4);
        const uint32_t sBaddr = sAaddr + (uint32_t)AWORDS * 4;

        // MODE 2: write normalized fp32 attn back (each element staged once)
        if (MODE == 2) {
#pragma unroll
            for (int c = 0; c < 2 * WGM; c++) {
                const int m = sm8 + c * 32;
                const uint4 d = *reinterpret_cast<const uint4*>(sA + m * 32 + w4);
                const float iv = invs[c];
                float2 f0 = __half22float2(*reinterpret_cast<const __half2*>(&d.x));
                float2 f1 = __half22float2(*reinterpret_cast<const __half2*>(&d.y));
                float2 f2 = __half22float2(*reinterpret_cast<const __half2*>(&d.z));
                float2 f3 = __half22float2(*reinterpret_cast<const __half2*>(&d.w));
                float4 o0 = make_float4(f0.x * iv, f0.y * iv, f1.x * iv, f1.y * iv);
                float4 o1 = make_float4(f2.x * iv, f2.y * iv, f3.x * iv, f3.y * iv);
                float* dst = aux + (bm + m) * (long)lda + it * 64 + skc * 8;
                *reinterpret_cast<float4*>(dst)     = o0;
                *reinterpret_cast<float4*>(dst + 4) = o1;
            }
        }

        // fragment loader for k16 step ks (0..3) via ldmatrix.x4
        auto load_frags = [&](int ks, uint32_t af[4][4], uint32_t bf[8][2]) {
#pragma unroll
            for (int mt = 0; mt < 4; mt++) {
                const int row = wm + mt * 16 + lrow;
                const int ch  = (2 * ks + lkh) ^ (row & 7);
                ldsm4(af[mt][0], af[mt][1], af[mt][2], af[mt][3],
                      sAaddr + (uint32_t)(row * 32 + ch * 4) * 4);
            }
#pragma unroll
            for (int p = 0; p < 4; p++) {
                const int row = wn + p * 16 + lrow;
                const int ch  = (2 * ks + lkh) ^ (row & 7);
                ldsm4(bf[2*p][0], bf[2*p+1][0], bf[2*p][1], bf[2*p+1][1],
                      sBaddr + (uint32_t)(row * 32 + ch * 4) * 4);
            }
        };

        uint32_t af[2][4][4], bf[2][8][2];
        load_frags(0, af[0], bf[0]);
#pragma unroll
        for (int ks = 0; ks < 4; ks++) {
            const int cur = ks & 1;
            if (ks < 3) load_frags(ks + 1, af[cur ^ 1], bf[cur ^ 1]);
#pragma unroll
            for (int mt = 0; mt < 4; mt++)
#pragma unroll
                for (int nt = 0; nt < 8; nt++)
                    mma_f16(acc[mt][nt][0], acc[mt][nt][1], acc[mt][nt][2], acc[mt][nt][3],
                            af[cur][mt][0], af[cur][mt][1], af[cur][mt][2], af[cur][mt][3],
                            bf[cur][nt][0], bf[cur][nt][1]);
        }
        cbuf++; if (cbuf >= NSTAGE) cbuf = 0;
    }

    // ---- epilogue ----
    if (MODE == 1) {
        __half* Ch = (__half*)Cv;
        const int ct = (int)((bn + wn) >> 6);
#pragma unroll
        for (int mt = 0; mt < 4; mt++) {
            const long r0 = bm + wm + mt * 16 + grp;
            float rs0 = 0.0f, rs1 = 0.0f;
#pragma unroll
            for (int nt = 0; nt < 8; nt++) {
                const int cn = (int)bn + wn + nt * 8 + 2 * tg;
                const float e00 = __expf(acc[mt][nt][0] * alpha);
                const float e01 = __expf(acc[mt][nt][1] * alpha);
                const float e10 = __expf(acc[mt][nt][2] * alpha);
                const float e11 = __expf(acc[mt][nt][3] * alpha);
                const __half2 h0 = __floats2half2_rn(e00, e01);
                const __half2 h1 = __floats2half2_rn(e10, e11);
                const float2 b0 = __half22float2(h0);
                const float2 b1 = __half22float2(h1);
                rs0 += b0.x + b0.y;
                rs1 += b1.x + b1.y;
                *reinterpret_cast<__half2*>(Ch + r0 * (long)ldc + cn)       = h0;
                *reinterpret_cast<__half2*>(Ch + (r0 + 8) * (long)ldc + cn) = h1;
            }
            rs0 += __shfl_xor_sync(0xffffffffu, rs0, 1);
            rs0 += __shfl_xor_sync(0xffffffffu, rs0, 2);
            rs1 += __shfl_xor_sync(0xffffffffu, rs1, 1);
            rs1 += __shfl_xor_sync(0xffffffffu, rs1, 2);
            if (tg == 0) {
                aux[(size_t)r0 * 64 + ct]       = rs0;
                aux[(size_t)(r0 + 8) * 64 + ct] = rs1;
            }
        }
    } else if (MODE == 3) {
        __half* Ch = (__half*)Cv;
#pragma unroll
        for (int mt = 0; mt < 4; mt++) {
            const long r0 = bm + wm + mt * 16 + grp;
#pragma unroll
            for (int nt = 0; nt < 8; nt++) {
                const int cn = (int)bn + wn + nt * 8 + 2 * tg;
                float v00 = acc[mt][nt][0] * alpha;
                float v01 = acc[mt][nt][1] * alpha;
                float v10 = acc[mt][nt][2] * alpha;
                float v11 = acc[mt][nt][3] * alpha;
                if (HASBIAS) {
                    const float b0 = bias[cn], b1 = bias[cn + 1];
                    v00 += b0; v01 += b1;
                    v10 += b0; v11 += b1;
                }
                Ch[(size_t)cn * ldc + r0]           = __float2half_rn(v00);
                Ch[(size_t)(cn + 1) * ldc + r0]     = __float2half_rn(v01);
                Ch[(size_t)cn * ldc + r0 + 8]       = __float2half_rn(v10);
                Ch[(size_t)(cn + 1) * ldc + r0 + 8] = __float2half_rn(v11);
            }
        }
    } else {
#pragma unroll
        for (int mt = 0; mt < 4; mt++) {
            const long r0 = bm + wm + mt * 16 + grp;
            float s0 = 1.0f, s1 = 1.0f;
            if (MODE == 2) { s0 = invrow[r0]; s1 = invrow[r0 + 8]; }
#pragma unroll
            for (int nt = 0; nt < 8; nt++) {
                const int cn = (int)bn + wn + nt * 8 + 2 * tg;
                float v00 = acc[mt][nt][0] * alpha * s0;
                float v01 = acc[mt][nt][1] * alpha * s0;
                float v10 = acc[mt][nt][2] * alpha * s1;
                float v11 = acc[mt][nt][3] * alpha * s1;
                if (HASBIAS) {
                    const float b0 = bias[cn], b1 = bias[cn + 1];
                    v00 += b0; v01 += b1;
                    v10 += b0; v11 += b1;
                }
                if (OUTHALF) {
                    __half* Ch = (__half*)Cv;
                    *reinterpret_cast<__half2*>(Ch + r0 * (long)ldc + cn)       = __floats2half2_rn(v00, v01);
                    *reinterpret_cast<__half2*>(Ch + (r0 + 8) * (long)ldc + cn) = __floats2half2_rn(v10, v11);
                } else {
                    float* Cf = (float*)Cv;
                    *reinterpret_cast<float2*>(Cf + r0 * (long)ldc + cn)       = make_float2(v00, v01);
                    *reinterpret_cast<float2*>(Cf + (r0 + 8) * (long)ldc + cn) = make_float2(v10, v11);
                }
            }
        }
    }
}

// ---------------------------------------------------------------------------
__global__ void __launch_bounds__(256) f2h_kernel(const float* __restrict__ q,
                                                  const float* __restrict__ k,
                                                  const float* __restrict__ v)
{
    const int z = blockIdx.y;
    const float* src = z == 0 ? q : z == 1 ? k : v;
    __half* dst = z == 0 ? g_qin : z == 1 ? g_kin : g_vin;
    const size_t i = (size_t)blockIdx.x * 256 + threadIdx.x;
    const float4 val = reinterpret_cast<const float4*>(src)[i];
    __half2 h0 = __floats2half2_rn(val.x, val.y);
    __half2 h1 = __floats2half2_rn(val.z, val.w);
    uint2 o;
    o.x = *reinterpret_cast<uint32_t*>(&h0);
    o.y = *reinterpret_cast<uint32_t*>(&h1);
    reinterpret_cast<uint2*>(dst)[i] = o;
}

// merged weight transpose: z 0..11 -> Wq/Wk/Wv heads (8 x-blocks), z=12 -> Wo
__global__ void __launch_bounds__(256) transw_kernel(
    const float* __restrict__ Wq, const float* __restrict__ Wk,
    const float* __restrict__ Wv, const float* __restrict__ Wo)
{
    __shared__ float t[32][33];
    const int z = blockIdx.z;
    const float* src;
    __half* dst;
    int R, C;
    if (z == 12) { src = Wo; dst = g_WoTh; R = DM; C = DM; }
    else {
        const int mat = z >> 2, head = z & 3;
        const float* W = mat == 0 ? Wq : mat == 1 ? Wk : Wv;
        src = W + (size_t)head * DM * DK;
        dst = g_WTh + (size_t)z * DK * DM;
        R = DM; C = DK;
        if (blockIdx.x >= 8) return;
    }

    const int c0 = blockIdx.x * 32, r0 = blockIdx.y * 32;
    const int tx = threadIdx.x & 31, ty = threadIdx.x >> 5;
#pragma unroll
    for (int i = 0; i < 4; i++)
        t[ty + i * 8][tx] = src[(size_t)(r0 + ty + i * 8) * C + c0 + tx];
    __syncthreads();
#pragma unroll
    for (int i = 0; i < 4; i++)
        dst[(size_t)(c0 + ty + i * 8) * R + r0 + tx] = __float2half_rn(t[tx][ty + i * 8]);
}

__global__ void __launch_bounds__(256) invsum_kernel()
{
    const int row  = blockIdx.x * 8 + (threadIdx.x >> 5);
    const int lane = threadIdx.x & 31;
    float s = g_psum[(size_t)row * 64 + lane] + g_psum[(size_t)row * 64 + 32 + lane];
#pragma unroll
    for (int o = 16; o > 0; o >>= 1) s += __shfl_xor_sync(0xffffffffu, s, o);
    if (lane == 0) g_invsum[row] = 1.0f / s;
}

// ---------------------------------------------------------------------------
// proj: z 0..3 Q heads, 4..7 K heads, 8..11 V heads (V written transposed)
// ---------------------------------------------------------------------------
__global__ void __launch_bounds__(256, 1) proj_tc(
    const float* __restrict__ bq, const float* __restrict__ bk, const float* __restrict__ bv)
{
    const int z = blockIdx.z, mat = z >> 2, head = z & 3;
    const __half* A    = mat == 0 ? g_qin : mat == 1 ? g_kin : g_vin;
    const __half* B    = g_WTh + (size_t)z * DK * DM;
    const float*  bias = (mat == 0 ? bq : mat == 1 ? bk : bv) + head * DK;
    if (mat == 2) {
        __half* C = g_VTh + (size_t)head * BS_TOT * DK;
        const long b = (long)blockIdx.y / 32;
        __half* Cb = C + b * SEQ * DK - b * SEQ;
        gemm_h<2, 4, true, true, 3>(A, DM, B, DM, Cb, SEQ, DM, 1.0f, bias, nullptr, nullptr);
    } else {
        __half* C = (mat == 0 ? g_Qh : g_Kh) + (size_t)head * BS_TOT * DK;
        gemm_h<2, 4, true, true, 0>(A, DM, B, DM, C, DK, DM, 1.0f, bias, nullptr, nullptr);
    }
}

__global__ void __launch_bounds__(256, 1) scores_tc()
{
    const int z = blockIdx.z;
    gemm_h<4, 2, false, true, 1>(g_Qh + (size_t)z * SEQ * DK, DK,
                                 g_Kh + (size_t)z * SEQ * DK, DK,
                                 g_Eh + (size_t)z * SEQ * SEQ, SEQ, DK, 0.0625f,
                                 nullptr, g_psum + (size_t)z * SEQ * 64, nullptr);
}

__global__ void __launch_bounds__(256, 1) av_tc(float* __restrict__ attn_out)
{
    float* attn = attn_out ? attn_out : g_attn_fallback;
    const int z = blockIdx.z, h = z >> 1, b = z & 1;
    gemm_h<2, 4, false, true, 2>(g_Eh + (size_t)z * SEQ * SEQ, SEQ,
                                 g_VTh + (size_t)z * DK * SEQ, SEQ,
                                 g_HOh + (size_t)b * SEQ * DM + h * DK, DM, SEQ, 1.0f,
                                 nullptr,
                                 attn + (size_t)z * SEQ * SEQ,
                                 g_invsum + (size_t)z * SEQ);
}

__global__ void __launch_bounds__(256, 1) outproj_tc(const float* __restrict__ bo,
                                                     float* __restrict__ out)
{
    gemm_h<2, 4, true, false, 0>(g_HOh, DM, g_WoTh, DM, out, DM, DM, 1.0f, bo,
                                 nullptr, nullptr);
}

// ---------------------------------------------------------------------------
extern "C" void kernel_launch(void* const* d_in, const int* in_sizes, int n_in,
                              void* d_out, int out_size)
{
    const float* q  = (const float*)d_in[0];
    const float* k  = (const float*)d_in[1];
    const float* v  = (const float*)d_in[2];
    const float* Wq = (const float*)d_in[3];
    const float* bq = (const float*)d_in[4];
    const float* Wk = (const float*)d_in[5];
    const float* bk = (const float*)d_in[6];
    const float* Wv = (const float*)d_in[7];
    const float* bv = (const float*)d_in[8];
    const float* Wo = (const float*)d_in[9];
    const float* bo = (const float*)d_in[10];

    float* out = (float*)d_out;
    const long OUT_ELEMS  = (long)NB * SEQ * DM;
    const long ATTN_ELEMS = (long)NH * NB * SEQ * SEQ;
    float* attn_out = nullptr;
    if ((long)out_size >= OUT_ELEMS + ATTN_ELEMS) attn_out = out + OUT_ELEMS;

    cudaFuncSetAttribute(proj_tc,    cudaFuncAttributeMaxDynamicSharedMemorySize, SMEM_BYTES);
    cudaFuncSetAttribute(scores_tc,  cudaFuncAttributeMaxDynamicSharedMemorySize, SMEM_BYTES);
    cudaFuncSetAttribute(av_tc,      cudaFuncAttributeMaxDynamicSharedMemorySize, SMEM_BYTES);
    cudaFuncSetAttribute(outproj_tc, cudaFuncAttributeMaxDynamicSharedMemorySize, SMEM_BYTES);

    f2h_kernel<<<dim3(BS_TOT * DM / 4 / 256, 3), 256>>>(q, k, v);

    transw_kernel<<<dim3(32, 32, 13), 256>>>(Wq, Wk, Wv, Wo);

    // proj (Q, K normal; V transposed directly into g_VTh)
    proj_tc<<<dim3(1, 64, 12), 256, SMEM_BYTES>>>(bq, bk, bv);

    // scores: exp(QK^T/16) fp16 + row partial sums
    scores_tc<<<dim3(32, 16, 8), 256, SMEM_BYTES>>>();

    invsum_kernel<<<dim3(NROWS / 8), 256>>>();

    // av: normalized attn (fp32 to d_out) + HO
    av_tc<<<dim3(1, 32, 8), 256, SMEM_BYTES>>>(attn_out);

    outproj_tc<<<dim3(4, 64, 1), 256, SMEM_BYTES>>>(bo, out);
}

// round 14
// speedup vs baseline: 1.0531x; 1.0531x over previous
#include <cuda_runtime.h>
#include <cuda_fp16.h>
#include <cstdint>
#include <math.h>

// ---------------------------------------------------------------------------
// LegalMultiHeadAttention — Round 14: R12 datapath (64-K stages, 3-stage
// cp.async, scalar-LDS frags + frag double-buffer, chunk-XOR swizzle)
// + split-K4 for av (wave-quantization fix: 256 CTAs/2 waves -> 1024/1.75)
//   with fp16 partial HO slabs + reduce kernel.
//   B=2, S=4096, D_MODEL=1024, H=4, D_K=256.
// ---------------------------------------------------------------------------

#define SEQ    4096
#define DK     256
#define DM     1024
#define NH     4
#define NB     2
#define BS_TOT (NB*SEQ)          // 8192
#define NROWS  (NH*NB*SEQ)       // 32768
#define KSLABS 4
#define KSLAB  (SEQ/KSLABS)      // 1024

__device__ __half g_qin[(size_t)BS_TOT*DM];
__device__ __half g_kin[(size_t)BS_TOT*DM];
__device__ __half g_vin[(size_t)BS_TOT*DM];
__device__ __half g_Qh [(size_t)NH*BS_TOT*DK];
__device__ __half g_Kh [(size_t)NH*BS_TOT*DK];
__device__ __half g_VTh[(size_t)NH*BS_TOT*DK];    // [z][DK][SEQ], written by proj
__device__ __half g_HOh[(size_t)BS_TOT*DM];
__device__ __half g_HOp[(size_t)KSLABS*BS_TOT*DM]; // split-K partial HO
__device__ __half g_WTh[(size_t)3*NH*DK*DM];
__device__ __half g_WoTh[(size_t)DM*DM];
__device__ __half g_Eh [(size_t)NH*NB*SEQ*SEQ];   // unnormalized exp
__device__ float  g_psum[(size_t)NROWS*64];
__device__ float  g_invsum[NROWS];
__device__ float  g_attn_fallback[(size_t)NH*NB*SEQ*SEQ];

__device__ __forceinline__ uint32_t smem_u32(const void* p) {
    uint32_t a;
    asm("{ .reg .u64 t; cvta.to.shared.u64 t, %1; cvt.u32.u64 %0, t; }"
        : "=r"(a) : "l"(p));
    return a;
}
__device__ __forceinline__ void mma_f16(float& c0, float& c1, float& c2, float& c3,
                                        uint32_t a0, uint32_t a1, uint32_t a2, uint32_t a3,
                                        uint32_t b0, uint32_t b1) {
    asm volatile(
        "mma.sync.aligned.m16n8k16.row.col.f32.f16.f16.f32 "
        "{%0,%1,%2,%3}, {%4,%5,%6,%7}, {%8,%9}, {%0,%1,%2,%3};"
        : "+f"(c0), "+f"(c1), "+f"(c2), "+f"(c3)
        : "r"(a0), "r"(a1), "r"(a2), "r"(a3), "r"(b0), "r"(b1));
}
__device__ __forceinline__ void cp16(uint32_t dst, const void* src) {
    asm volatile("cp.async.cg.shared.global [%0], [%1], 16;" :: "r"(dst), "l"(src));
}

#define NSTAGE 3
#define BUF_WORDS 12288                      // 384 rows * 32 words (64 fp16)
#define SMEM_BYTES (NSTAGE*BUF_WORDS*4)      // 147456

// ---------------------------------------------------------------------------
// fp16 GEMM NT: C[m,n] = alpha*sum_k A[m,k]*B[n,k] (+bias[n]).
// 256 threads = 8 warps (WGM x WGN), warp tile 64x64, K staged 64/stage.
// smem row = 32 words (64 halves); 16B chunk c stored at c ^ (row&7).
// MODE 0 plain | 1 scores (exp+psum) | 2 av (attn writeback + invrow scale)
//      | 3 transposed fp16 store C[n][m] (ldc = M-stride) for V^T.
// SPLITK: blockIdx.x is a k-slab index (bn forced 0); caller pre-offsets
//         A/B/C/aux pointers per slab.
// K must be a multiple of 64.
// ---------------------------------------------------------------------------
template<int WGM, int WGN, bool HASBIAS, bool OUTHALF, int MODE, bool SPLITK>
__device__ __forceinline__ void gemm_h(const __half* __restrict__ A, int lda,
                                       const __half* __restrict__ B, int ldb,
                                       void* __restrict__ Cv, int ldc,
                                       int K, float alpha, const float* __restrict__ bias,
                                       float* __restrict__ aux,
                                       const float* __restrict__ invrow)
{
    extern __shared__ uint32_t smem[];
    const uint32_t sbase = smem_u32(smem);

    const int tid  = threadIdx.x;           // 256
    const int wid  = tid >> 5;
    const int lane = tid & 31;
    const int grp  = lane >> 2;
    const int tg   = lane & 3;
    const int wm   = (wid / WGN) * 64;
    const int wn   = (wid % WGN) * 64;

    const long bm = (long)blockIdx.y * (WGM * 64);
    const long bn = SPLITK ? 0 : (long)blockIdx.x * (WGN * 64);
    A += bm * (long)lda;
    B += bn * (long)ldb;

    const int sm8 = tid >> 3;                // 0..31 (row within 32-row pass)
    const int skc = tid & 7;                 // 16B chunk 0..7
    const int w4  = (skc ^ (sm8 & 7)) * 4;   // swizzled chunk word offset

    float invs[2 * WGM];
    if (MODE == 2) {
#pragma unroll
        for (int c = 0; c < 2 * WGM; c++)
            invs[c] = invrow[bm + sm8 + c * 32];
    }

    float acc[4][8][4];
#pragma unroll
    for (int i = 0; i < 4; i++)
#pragma unroll
        for (int j = 0; j < 8; j++)
#pragma unroll
            for (int r = 0; r < 4; r++) acc[i][j][r] = 0.0f;

    const int NIT = K >> 6;
    const int AWORDS = WGM * 64 * 32;

    auto stage_copy = [&](int stage, int buf) {
        const uint32_t db = sbase + (uint32_t)buf * (BUF_WORDS * 4);
        const __half* Ak = A + stage * 64 + skc * 8;
        const __half* Bk = B + stage * 64 + skc * 8;
#pragma unroll
        for (int c = 0; c < 2 * WGM; c++) {
            const int r = sm8 + c * 32;
            cp16(db + (uint32_t)(r * 32 + w4) * 4, Ak + (long)r * lda);
        }
        const uint32_t dbB = db + (uint32_t)AWORDS * 4;
#pragma unroll
        for (int c = 0; c < 2 * WGN; c++) {
            const int r = sm8 + c * 32;
            cp16(dbB + (uint32_t)(r * 32 + w4) * 4, Bk + (long)r * ldb);
        }
        asm volatile("cp.async.commit_group;" ::: "memory");
    };

    stage_copy(0, 0);
    stage_copy(1, 1);

    int cbuf = 0;
#pragma unroll 1
    for (int it = 0; it < NIT; it++) {
        asm volatile("cp.async.wait_group %0;" :: "n"(NSTAGE - 2) : "memory");
        __syncthreads();
        if (it + 2 < NIT) {
            int nb = cbuf + 2; if (nb >= NSTAGE) nb -= NSTAGE;
            stage_copy(it + 2, nb);
        }

        const uint32_t* sA = smem + cbuf * BUF_WORDS;
        const uint32_t* sB = sA + AWORDS;

        // MODE 2: write normalized fp32 attn back (each element staged once)
        if (MODE == 2) {
#pragma unroll
            for (int c = 0; c < 2 * WGM; c++) {
                const int m = sm8 + c * 32;
                const uint4 d = *reinterpret_cast<const uint4*>(sA + m * 32 + w4);
                const float iv = invs[c];
                float2 f0 = __half22float2(*reinterpret_cast<const __half2*>(&d.x));
                float2 f1 = __half22float2(*reinterpret_cast<const __half2*>(&d.y));
                float2 f2 = __half22float2(*reinterpret_cast<const __half2*>(&d.z));
                float2 f3 = __half22float2(*reinterpret_cast<const __half2*>(&d.w));
                float4 o0 = make_float4(f0.x * iv, f0.y * iv, f1.x * iv, f1.y * iv);
                float4 o1 = make_float4(f2.x * iv, f2.y * iv, f3.x * iv, f3.y * iv);
                float* dst = aux + (bm + m) * (long)lda + it * 64 + skc * 8;
                *reinterpret_cast<float4*>(dst)     = o0;
                *reinterpret_cast<float4*>(dst + 4) = o1;
            }
        }

        // fragment loader for k16 step ks (0..3); all rows ≡ grp (mod 8)
        auto load_frags = [&](int ks, uint32_t af[4][4], uint32_t bf[8][2]) {
            const int sw0 = ((2 * ks)     ^ grp) * 4 + tg;
            const int sw1 = ((2 * ks + 1) ^ grp) * 4 + tg;
#pragma unroll
            for (int mt = 0; mt < 4; mt++) {
                const int r0 = (wm + mt * 16 + grp) * 32;
                const int r1 = r0 + 8 * 32;
                af[mt][0] = sA[r0 + sw0];
                af[mt][1] = sA[r1 + sw0];
                af[mt][2] = sA[r0 + sw1];
                af[mt][3] = sA[r1 + sw1];
            }
#pragma unroll
            for (int nt = 0; nt < 8; nt++) {
                const int rb = (wn + nt * 8 + grp) * 32;
                bf[nt][0] = sB[rb + sw0];
                bf[nt][1] = sB[rb + sw1];
            }
        };

        uint32_t af[2][4][4], bf[2][8][2];
        load_frags(0, af[0], bf[0]);
#pragma unroll
        for (int ks = 0; ks < 4; ks++) {
            const int cur = ks & 1;
            if (ks < 3) load_frags(ks + 1, af[cur ^ 1], bf[cur ^ 1]);
#pragma unroll
            for (int mt = 0; mt < 4; mt++)
#pragma unroll
                for (int nt = 0; nt < 8; nt++)
                    mma_f16(acc[mt][nt][0], acc[mt][nt][1], acc[mt][nt][2], acc[mt][nt][3],
                            af[cur][mt][0], af[cur][mt][1], af[cur][mt][2], af[cur][mt][3],
                            bf[cur][nt][0], bf[cur][nt][1]);
        }
        cbuf++; if (cbuf >= NSTAGE) cbuf = 0;
    }

    // ---- epilogue ----
    if (MODE == 1) {
        __half* Ch = (__half*)Cv;
        const int ct = (int)((bn + wn) >> 6);
#pragma unroll
        for (int mt = 0; mt < 4; mt++) {
            const long r0 = bm + wm + mt * 16 + grp;
            float rs0 = 0.0f, rs1 = 0.0f;
#pragma unroll
            for (int nt = 0; nt < 8; nt++) {
                const int cn = (int)bn + wn + nt * 8 + 2 * tg;
                const float e00 = __expf(acc[mt][nt][0] * alpha);
                const float e01 = __expf(acc[mt][nt][1] * alpha);
                const float e10 = __expf(acc[mt][nt][2] * alpha);
                const float e11 = __expf(acc[mt][nt][3] * alpha);
                const __half2 h0 = __floats2half2_rn(e00, e01);
                const __half2 h1 = __floats2half2_rn(e10, e11);
                const float2 b0 = __half22float2(h0);
                const float2 b1 = __half22float2(h1);
                rs0 += b0.x + b0.y;
                rs1 += b1.x + b1.y;
                *reinterpret_cast<__half2*>(Ch + r0 * (long)ldc + cn)       = h0;
                *reinterpret_cast<__half2*>(Ch + (r0 + 8) * (long)ldc + cn) = h1;
            }
            rs0 += __shfl_xor_sync(0xffffffffu, rs0, 1);
            rs0 += __shfl_xor_sync(0xffffffffu, rs0, 2);
            rs1 += __shfl_xor_sync(0xffffffffu, rs1, 1);
            rs1 += __shfl_xor_sync(0xffffffffu, rs1, 2);
            if (tg == 0) {
                aux[(size_t)r0 * 64 + ct]       = rs0;
                aux[(size_t)(r0 + 8) * 64 + ct] = rs1;
            }
        }
    } else if (MODE == 3) {
        __half* Ch = (__half*)Cv;
#pragma unroll
        for (int mt = 0; mt < 4; mt++) {
            const long r0 = bm + wm + mt * 16 + grp;
#pragma unroll
            for (int nt = 0; nt < 8; nt++) {
                const int cn = (int)bn + wn + nt * 8 + 2 * tg;
                float v00 = acc[mt][nt][0] * alpha;
                float v01 = acc[mt][nt][1] * alpha;
                float v10 = acc[mt][nt][2] * alpha;
                float v11 = acc[mt][nt][3] * alpha;
                if (HASBIAS) {
                    const float b0 = bias[cn], b1 = bias[cn + 1];
                    v00 += b0; v01 += b1;
                    v10 += b0; v11 += b1;
                }
                Ch[(size_t)cn * ldc + r0]           = __float2half_rn(v00);
                Ch[(size_t)(cn + 1) * ldc + r0]     = __float2half_rn(v01);
                Ch[(size_t)cn * ldc + r0 + 8]       = __float2half_rn(v10);
                Ch[(size_t)(cn + 1) * ldc + r0 + 8] = __float2half_rn(v11);
            }
        }
    } else {
#pragma unroll
        for (int mt = 0; mt < 4; mt++) {
            const long r0 = bm + wm + mt * 16 + grp;
            float s0 = 1.0f, s1 = 1.0f;
            if (MODE == 2) { s0 = invrow[r0]; s1 = invrow[r0 + 8]; }
#pragma unroll
            for (int nt = 0; nt < 8; nt++) {
                const int cn = (int)bn + wn + nt * 8 + 2 * tg;
                float v00 = acc[mt][nt][0] * alpha * s0;
                float v01 = acc[mt][nt][1] * alpha * s0;
                float v10 = acc[mt][nt][2] * alpha * s1;
                float v11 = acc[mt][nt][3] * alpha * s1;
                if (HASBIAS) {
                    const float b0 = bias[cn], b1 = bias[cn + 1];
                    v00 += b0; v01 += b1;
                    v10 += b0; v11 += b1;
                }
                if (OUTHALF) {
                    __half* Ch = (__half*)Cv;
                    *reinterpret_cast<__half2*>(Ch + r0 * (long)ldc + cn)       = __floats2half2_rn(v00, v01);
                    *reinterpret_cast<__half2*>(Ch + (r0 + 8) * (long)ldc + cn) = __floats2half2_rn(v10, v11);
                } else {
                    float* Cf = (float*)Cv;
                    *reinterpret_cast<float2*>(Cf + r0 * (long)ldc + cn)       = make_float2(v00, v01);
                    *reinterpret_cast<float2*>(Cf + (r0 + 8) * (long)ldc + cn) = make_float2(v10, v11);
                }
            }
        }
    }
}

// ---------------------------------------------------------------------------
__global__ void __launch_bounds__(256) f2h_kernel(const float* __restrict__ q,
                                                  const float* __restrict__ k,
                                                  const float* __restrict__ v)
{
    const int z = blockIdx.y;
    const float* src = z == 0 ? q : z == 1 ? k : v;
    __half* dst = z == 0 ? g_qin : z == 1 ? g_kin : g_vin;
    const size_t i = (size_t)blockIdx.x * 256 + threadIdx.x;
    const float4 val = reinterpret_cast<const float4*>(src)[i];
    __half2 h0 = __floats2half2_rn(val.x, val.y);
    __half2 h1 = __floats2half2_rn(val.z, val.w);
    uint2 o;
    o.x = *reinterpret_cast<uint32_t*>(&h0);
    o.y = *reinterpret_cast<uint32_t*>(&h1);
    reinterpret_cast<uint2*>(dst)[i] = o;
}

// merged weight transpose: z 0..11 -> Wq/Wk/Wv heads (8 x-blocks), z=12 -> Wo
__global__ void __launch_bounds__(256) transw_kernel(
    const float* __restrict__ Wq, const float* __restrict__ Wk,
    const float* __restrict__ Wv, const float* __restrict__ Wo)
{
    __shared__ float t[32][33];
    const int z = blockIdx.z;
    const float* src;
    __half* dst;
    int R, C;
    if (z == 12) { src = Wo; dst = g_WoTh; R = DM; C = DM; }
    else {
        const int mat = z >> 2, head = z & 3;
        const float* W = mat == 0 ? Wq : mat == 1 ? Wk : Wv;
        src = W + (size_t)head * DM * DK;
        dst = g_WTh + (size_t)z * DK * DM;
        R = DM; C = DK;
        if (blockIdx.x >= 8) return;
    }

    const int c0 = blockIdx.x * 32, r0 = blockIdx.y * 32;
    const int tx = threadIdx.x & 31, ty = threadIdx.x >> 5;
#pragma unroll
    for (int i = 0; i < 4; i++)
        t[ty + i * 8][tx] = src[(size_t)(r0 + ty + i * 8) * C + c0 + tx];
    __syncthreads();
#pragma unroll
    for (int i = 0; i < 4; i++)
        dst[(size_t)(c0 + ty + i * 8) * R + r0 + tx] = __float2half_rn(t[tx][ty + i * 8]);
}

__global__ void __launch_bounds__(256) invsum_kernel()
{
    const int row  = blockIdx.x * 8 + (threadIdx.x >> 5);
    const int lane = threadIdx.x & 31;
    float s = g_psum[(size_t)row * 64 + lane] + g_psum[(size_t)row * 64 + 32 + lane];
#pragma unroll
    for (int o = 16; o > 0; o >>= 1) s += __shfl_xor_sync(0xffffffffu, s, o);
    if (lane == 0) g_invsum[row] = 1.0f / s;
}

// sum the 4 HO k-slab partials -> g_HOh (half2 granularity)
__global__ void __launch_bounds__(256) hored_kernel()
{
    const size_t n2 = (size_t)BS_TOT * DM / 2;
    const size_t i  = (size_t)blockIdx.x * 256 + threadIdx.x;
    const __half2* p = reinterpret_cast<const __half2*>(g_HOp);
    float2 s = __half22float2(p[i]);
    float2 a1 = __half22float2(p[i + n2]);
    float2 a2 = __half22float2(p[i + 2 * n2]);
    float2 a3 = __half22float2(p[i + 3 * n2]);
    s.x += a1.x + a2.x + a3.x;
    s.y += a1.y + a2.y + a3.y;
    reinterpret_cast<__half2*>(g_HOh)[i] = __floats2half2_rn(s.x, s.y);
}

// ---------------------------------------------------------------------------
// proj: z 0..3 Q heads, 4..7 K heads, 8..11 V heads (V written transposed)
// ---------------------------------------------------------------------------
__global__ void __launch_bounds__(256, 1) proj_tc(
    const float* __restrict__ bq, const float* __restrict__ bk, const float* __restrict__ bv)
{
    const int z = blockIdx.z, mat = z >> 2, head = z & 3;
    const __half* A    = mat == 0 ? g_qin : mat == 1 ? g_kin : g_vin;
    const __half* B    = g_WTh + (size_t)z * DK * DM;
    const float*  bias = (mat == 0 ? bq : mat == 1 ? bk : bv) + head * DK;
    if (mat == 2) {
        __half* C = g_VTh + (size_t)head * BS_TOT * DK;
        const long b = (long)blockIdx.y / 32;
        __half* Cb = C + b * SEQ * DK - b * SEQ;
        gemm_h<2, 4, true, true, 3, false>(A, DM, B, DM, Cb, SEQ, DM, 1.0f, bias, nullptr, nullptr);
    } else {
        __half* C = (mat == 0 ? g_Qh : g_Kh) + (size_t)head * BS_TOT * DK;
        gemm_h<2, 4, true, true, 0, false>(A, DM, B, DM, C, DK, DM, 1.0f, bias, nullptr, nullptr);
    }
}

__global__ void __launch_bounds__(256, 1) scores_tc()
{
    const int z = blockIdx.z;
    gemm_h<4, 2, false, true, 1, false>(g_Qh + (size_t)z * SEQ * DK, DK,
                                        g_Kh + (size_t)z * SEQ * DK, DK,
                                        g_Eh + (size_t)z * SEQ * SEQ, SEQ, DK, 0.0625f,
                                        nullptr, g_psum + (size_t)z * SEQ * 64, nullptr);
}

// av split-K4: blockIdx.x = k-slab; writes fp16 partial HO + its attn columns
__global__ void __launch_bounds__(256, 1) av_tc(float* __restrict__ attn_out)
{
    float* attn = attn_out ? attn_out : g_attn_fallback;
    const int z = blockIdx.z, h = z >> 1, b = z & 1;
    const int slab = blockIdx.x;
    const __half* A = g_Eh + (size_t)z * SEQ * SEQ + (size_t)slab * KSLAB;
    const __half* B = g_VTh + (size_t)z * DK * SEQ + (size_t)slab * KSLAB;
    __half* C = g_HOp + (size_t)slab * BS_TOT * DM + (size_t)b * SEQ * DM + h * DK;
    float* aux = attn + (size_t)z * SEQ * SEQ + (size_t)slab * KSLAB;
    gemm_h<2, 4, false, true, 2, true>(A, SEQ, B, SEQ, C, DM, KSLAB, 1.0f,
                                       nullptr, aux, g_invsum + (size_t)z * SEQ);
}

__global__ void __launch_bounds__(256, 1) outproj_tc(const float* __restrict__ bo,
                                                     float* __restrict__ out)
{
    gemm_h<2, 4, true, false, 0, false>(g_HOh, DM, g_WoTh, DM, out, DM, DM, 1.0f, bo,
                                        nullptr, nullptr);
}

// ---------------------------------------------------------------------------
extern "C" void kernel_launch(void* const* d_in, const int* in_sizes, int n_in,
                              void* d_out, int out_size)
{
    const float* q  = (const float*)d_in[0];
    const float* k  = (const float*)d_in[1];
    const float* v  = (const float*)d_in[2];
    const float* Wq = (const float*)d_in[3];
    const float* bq = (const float*)d_in[4];
    const float* Wk = (const float*)d_in[5];
    const float* bk = (const float*)d_in[6];
    const float* Wv = (const float*)d_in[7];
    const float* bv = (const float*)d_in[8];
    const float* Wo = (const float*)d_in[9];
    const float* bo = (const float*)d_in[10];

    float* out = (float*)d_out;
    const long OUT_ELEMS  = (long)NB * SEQ * DM;
    const long ATTN_ELEMS = (long)NH * NB * SEQ * SEQ;
    float* attn_out = nullptr;
    if ((long)out_size >= OUT_ELEMS + ATTN_ELEMS) attn_out = out + OUT_ELEMS;

    cudaFuncSetAttribute(proj_tc,    cudaFuncAttributeMaxDynamicSharedMemorySize, SMEM_BYTES);
    cudaFuncSetAttribute(scores_tc,  cudaFuncAttributeMaxDynamicSharedMemorySize, SMEM_BYTES);
    cudaFuncSetAttribute(av_tc,      cudaFuncAttributeMaxDynamicSharedMemorySize, SMEM_BYTES);
    cudaFuncSetAttribute(outproj_tc, cudaFuncAttributeMaxDynamicSharedMemorySize, SMEM_BYTES);

    f2h_kernel<<<dim3(BS_TOT * DM / 4 / 256, 3), 256>>>(q, k, v);

    transw_kernel<<<dim3(32, 32, 13), 256>>>(Wq, Wk, Wv, Wo);

    // proj (Q, K normal; V transposed directly into g_VTh)
    proj_tc<<<dim3(1, 64, 12), 256, SMEM_BYTES>>>(bq, bk, bv);

    // scores: exp(QK^T/16) fp16 + row partial sums
    scores_tc<<<dim3(32, 16, 8), 256, SMEM_BYTES>>>();

    invsum_kernel<<<dim3(NROWS / 8), 256>>>();

    // av: split-K4 -> fp16 HO partials + normalized attn (fp32 to d_out)
    av_tc<<<dim3(KSLABS, 32, 8), 256, SMEM_BYTES>>>(attn_out);

    // reduce HO partials
    hored_kernel<<<dim3(BS_TOT * DM / 2 / 256), 256>>>();

    outproj_tc<<<dim3(4, 64, 1), 256, SMEM_BYTES>>>(bo, out);
}

// round 15
// speedup vs baseline: 1.0930x; 1.0379x over previous
#include <cuda_runtime.h>
#include <cuda_fp16.h>
#include <cstdint>
#include <math.h>

// ---------------------------------------------------------------------------
// LegalMultiHeadAttention — Round 15: 2-CTA/SM GEMM (gemm_h2: 128x128 CTA,
// warp tile 64x32, <=128 regs, 96KB smem) for proj/scores/outproj; av keeps
// the 64x64 MODE-2 split-K4 path. fp16 m16n8k16, 64-K stages, 3-stage cp.async.
//   B=2, S=4096, D_MODEL=1024, H=4, D_K=256.
// ---------------------------------------------------------------------------

#define SEQ    4096
#define DK     256
#define DM     1024
#define NH     4
#define NB     2
#define BS_TOT (NB*SEQ)          // 8192
#define NROWS  (NH*NB*SEQ)       // 32768
#define KSLABS 4
#define KSLAB  (SEQ/KSLABS)      // 1024
#define PS     128               // psum slots per row (32-col granularity)

__device__ __half g_qin[(size_t)BS_TOT*DM];
__device__ __half g_kin[(size_t)BS_TOT*DM];
__device__ __half g_vin[(size_t)BS_TOT*DM];
__device__ __half g_Qh [(size_t)NH*BS_TOT*DK];
__device__ __half g_Kh [(size_t)NH*BS_TOT*DK];
__device__ __half g_VTh[(size_t)NH*BS_TOT*DK];    // [z][DK][SEQ], written by proj
__device__ __half g_HOh[(size_t)BS_TOT*DM];
__device__ __half g_HOp[(size_t)KSLABS*BS_TOT*DM]; // split-K partial HO
__device__ __half g_WTh[(size_t)3*NH*DK*DM];
__device__ __half g_WoTh[(size_t)DM*DM];
__device__ __half g_Eh [(size_t)NH*NB*SEQ*SEQ];   // unnormalized exp
__device__ float  g_psum[(size_t)NROWS*PS];
__device__ float  g_invsum[NROWS];
__device__ float  g_attn_fallback[(size_t)NH*NB*SEQ*SEQ];

__device__ __forceinline__ uint32_t smem_u32(const void* p) {
    uint32_t a;
    asm("{ .reg .u64 t; cvta.to.shared.u64 t, %1; cvt.u32.u64 %0, t; }"
        : "=r"(a) : "l"(p));
    return a;
}
__device__ __forceinline__ void mma_f16(float& c0, float& c1, float& c2, float& c3,
                                        uint32_t a0, uint32_t a1, uint32_t a2, uint32_t a3,
                                        uint32_t b0, uint32_t b1) {
    asm volatile(
        "mma.sync.aligned.m16n8k16.row.col.f32.f16.f16.f32 "
        "{%0,%1,%2,%3}, {%4,%5,%6,%7}, {%8,%9}, {%0,%1,%2,%3};"
        : "+f"(c0), "+f"(c1), "+f"(c2), "+f"(c3)
        : "r"(a0), "r"(a1), "r"(a2), "r"(a3), "r"(b0), "r"(b1));
}
__device__ __forceinline__ void cp16(uint32_t dst, const void* src) {
    asm volatile("cp.async.cg.shared.global [%0], [%1], 16;" :: "r"(dst), "l"(src));
}

// ---- av path (64x64 warp tile, 1 CTA/SM) ----
#define NSTAGE 3
#define BUF_WORDS 12288                      // 384 rows * 32 words
#define SMEM_BYTES (NSTAGE*BUF_WORDS*4)      // 147456

// ---- h2 path (128x128 CTA, 2 CTA/SM) ----
#define BUF2_WORDS 8192                      // 256 rows * 32 words
#define SMEM2_BYTES (NSTAGE*BUF2_WORDS*4)    // 98304

// ---------------------------------------------------------------------------
// gemm_h: 8 warps (WGM x WGN), warp tile 64x64 — used only for av (MODE 2).
// ---------------------------------------------------------------------------
template<int WGM, int WGN, bool HASBIAS, bool OUTHALF, int MODE, bool SPLITK>
__device__ __forceinline__ void gemm_h(const __half* __restrict__ A, int lda,
                                       const __half* __restrict__ B, int ldb,
                                       void* __restrict__ Cv, int ldc,
                                       int K, float alpha, const float* __restrict__ bias,
                                       float* __restrict__ aux,
                                       const float* __restrict__ invrow)
{
    extern __shared__ uint32_t smem[];
    const uint32_t sbase = smem_u32(smem);

    const int tid  = threadIdx.x;
    const int wid  = tid >> 5;
    const int lane = tid & 31;
    const int grp  = lane >> 2;
    const int tg   = lane & 3;
    const int wm   = (wid / WGN) * 64;
    const int wn   = (wid % WGN) * 64;

    const long bm = (long)blockIdx.y * (WGM * 64);
    const long bn = SPLITK ? 0 : (long)blockIdx.x * (WGN * 64);
    A += bm * (long)lda;
    B += bn * (long)ldb;

    const int sm8 = tid >> 3;
    const int skc = tid & 7;
    const int w4  = (skc ^ (sm8 & 7)) * 4;

    float invs[2 * WGM];
    if (MODE == 2) {
#pragma unroll
        for (int c = 0; c < 2 * WGM; c++)
            invs[c] = invrow[bm + sm8 + c * 32];
    }

    float acc[4][8][4];
#pragma unroll
    for (int i = 0; i < 4; i++)
#pragma unroll
        for (int j = 0; j < 8; j++)
#pragma unroll
            for (int r = 0; r < 4; r++) acc[i][j][r] = 0.0f;

    const int NIT = K >> 6;
    const int AWORDS = WGM * 64 * 32;

    auto stage_copy = [&](int stage, int buf) {
        const uint32_t db = sbase + (uint32_t)buf * (BUF_WORDS * 4);
        const __half* Ak = A + stage * 64 + skc * 8;
        const __half* Bk = B + stage * 64 + skc * 8;
#pragma unroll
        for (int c = 0; c < 2 * WGM; c++) {
            const int r = sm8 + c * 32;
            cp16(db + (uint32_t)(r * 32 + w4) * 4, Ak + (long)r * lda);
        }
        const uint32_t dbB = db + (uint32_t)AWORDS * 4;
#pragma unroll
        for (int c = 0; c < 2 * WGN; c++) {
            const int r = sm8 + c * 32;
            cp16(dbB + (uint32_t)(r * 32 + w4) * 4, Bk + (long)r * ldb);
        }
        asm volatile("cp.async.commit_group;" ::: "memory");
    };

    stage_copy(0, 0);
    stage_copy(1, 1);

    int cbuf = 0;
#pragma unroll 1
    for (int it = 0; it < NIT; it++) {
        asm volatile("cp.async.wait_group %0;" :: "n"(NSTAGE - 2) : "memory");
        __syncthreads();
        if (it + 2 < NIT) {
            int nb = cbuf + 2; if (nb >= NSTAGE) nb -= NSTAGE;
            stage_copy(it + 2, nb);
        }

        const uint32_t* sA = smem + cbuf * BUF_WORDS;
        const uint32_t* sB = sA + AWORDS;

        if (MODE == 2) {
#pragma unroll
            for (int c = 0; c < 2 * WGM; c++) {
                const int m = sm8 + c * 32;
                const uint4 d = *reinterpret_cast<const uint4*>(sA + m * 32 + w4);
                const float iv = invs[c];
                float2 f0 = __half22float2(*reinterpret_cast<const __half2*>(&d.x));
                float2 f1 = __half22float2(*reinterpret_cast<const __half2*>(&d.y));
                float2 f2 = __half22float2(*reinterpret_cast<const __half2*>(&d.z));
                float2 f3 = __half22float2(*reinterpret_cast<const __half2*>(&d.w));
                float4 o0 = make_float4(f0.x * iv, f0.y * iv, f1.x * iv, f1.y * iv);
                float4 o1 = make_float4(f2.x * iv, f2.y * iv, f3.x * iv, f3.y * iv);
                float* dst = aux + (bm + m) * (long)lda + it * 64 + skc * 8;
                *reinterpret_cast<float4*>(dst)     = o0;
                *reinterpret_cast<float4*>(dst + 4) = o1;
            }
        }

        auto load_frags = [&](int ks, uint32_t af[4][4], uint32_t bf[8][2]) {
            const int sw0 = ((2 * ks)     ^ grp) * 4 + tg;
            const int sw1 = ((2 * ks + 1) ^ grp) * 4 + tg;
#pragma unroll
            for (int mt = 0; mt < 4; mt++) {
                const int r0 = (wm + mt * 16 + grp) * 32;
                const int r1 = r0 + 8 * 32;
                af[mt][0] = sA[r0 + sw0];
                af[mt][1] = sA[r1 + sw0];
                af[mt][2] = sA[r0 + sw1];
                af[mt][3] = sA[r1 + sw1];
            }
#pragma unroll
            for (int nt = 0; nt < 8; nt++) {
                const int rb = (wn + nt * 8 + grp) * 32;
                bf[nt][0] = sB[rb + sw0];
                bf[nt][1] = sB[rb + sw1];
            }
        };

        uint32_t af[2][4][4], bf[2][8][2];
        load_frags(0, af[0], bf[0]);
#pragma unroll
        for (int ks = 0; ks < 4; ks++) {
            const int cur = ks & 1;
            if (ks < 3) load_frags(ks + 1, af[cur ^ 1], bf[cur ^ 1]);
#pragma unroll
            for (int mt = 0; mt < 4; mt++)
#pragma unroll
                for (int nt = 0; nt < 8; nt++)
                    mma_f16(acc[mt][nt][0], acc[mt][nt][1], acc[mt][nt][2], acc[mt][nt][3],
                            af[cur][mt][0], af[cur][mt][1], af[cur][mt][2], af[cur][mt][3],
                            bf[cur][nt][0], bf[cur][nt][1]);
        }
        cbuf++; if (cbuf >= NSTAGE) cbuf = 0;
    }

    // epilogue (only MODE 2 / plain used by av path)
#pragma unroll
    for (int mt = 0; mt < 4; mt++) {
        const long r0 = bm + wm + mt * 16 + grp;
        float s0 = 1.0f, s1 = 1.0f;
        if (MODE == 2) { s0 = invrow[r0]; s1 = invrow[r0 + 8]; }
#pragma unroll
        for (int nt = 0; nt < 8; nt++) {
            const int cn = (int)bn + wn + nt * 8 + 2 * tg;
            float v00 = acc[mt][nt][0] * alpha * s0;
            float v01 = acc[mt][nt][1] * alpha * s0;
            float v10 = acc[mt][nt][2] * alpha * s1;
            float v11 = acc[mt][nt][3] * alpha * s1;
            if (HASBIAS) {
                const float b0 = bias[cn], b1 = bias[cn + 1];
                v00 += b0; v01 += b1;
                v10 += b0; v11 += b1;
            }
            if (OUTHALF) {
                __half* Ch = (__half*)Cv;
                *reinterpret_cast<__half2*>(Ch + r0 * (long)ldc + cn)       = __floats2half2_rn(v00, v01);
                *reinterpret_cast<__half2*>(Ch + (r0 + 8) * (long)ldc + cn) = __floats2half2_rn(v10, v11);
            } else {
                float* Cf = (float*)Cv;
                *reinterpret_cast<float2*>(Cf + r0 * (long)ldc + cn)       = make_float2(v00, v01);
                *reinterpret_cast<float2*>(Cf + (r0 + 8) * (long)ldc + cn) = make_float2(v10, v11);
            }
        }
    }
}

// ---------------------------------------------------------------------------
// gemm_h2: CTA 128x128, 8 warps as 2(M) x 4(N), warp tile 64x32, <=128 regs,
// no frag double-buffer (latency hidden by 2 CTAs/SM). 3-stage cp.async.
// MODE 0 plain | 1 scores (exp + 32-col psum) | 3 transposed fp16 store.
// ---------------------------------------------------------------------------
template<bool HASBIAS, bool OUTHALF, int MODE>
__device__ __forceinline__ void gemm_h2(const __half* __restrict__ A, int lda,
                                        const __half* __restrict__ B, int ldb,
                                        void* __restrict__ Cv, int ldc,
                                        int K, float alpha, const float* __restrict__ bias,
                                        float* __restrict__ aux)
{
    extern __shared__ uint32_t smem[];
    const uint32_t sbase = smem_u32(smem);

    const int tid  = threadIdx.x;           // 256
    const int wid  = tid >> 5;
    const int lane = tid & 31;
    const int grp  = lane >> 2;
    const int tg   = lane & 3;
    const int wm   = (wid >> 2) * 64;        // 0,64
    const int wn   = (wid & 3) * 32;         // 0,32,64,96

    const long bm = (long)blockIdx.y * 128;
    const long bn = (long)blockIdx.x * 128;
    A += bm * (long)lda;
    B += bn * (long)ldb;

    const int sm8 = tid >> 3;
    const int skc = tid & 7;
    const int w4  = (skc ^ (sm8 & 7)) * 4;

    float acc[4][4][4];
#pragma unroll
    for (int i = 0; i < 4; i++)
#pragma unroll
        for (int j = 0; j < 4; j++)
#pragma unroll
            for (int r = 0; r < 4; r++) acc[i][j][r] = 0.0f;

    const int NIT = K >> 6;
    const int AWORDS = 128 * 32;             // 4096

    auto stage_copy = [&](int stage, int buf) {
        const uint32_t db = sbase + (uint32_t)buf * (BUF2_WORDS * 4);
        const __half* Ak = A + stage * 64 + skc * 8;
        const __half* Bk = B + stage * 64 + skc * 8;
#pragma unroll
        for (int c = 0; c < 4; c++) {
            const int r = sm8 + c * 32;
            cp16(db + (uint32_t)(r * 32 + w4) * 4, Ak + (long)r * lda);
        }
        const uint32_t dbB = db + (uint32_t)AWORDS * 4;
#pragma unroll
        for (int c = 0; c < 4; c++) {
            const int r = sm8 + c * 32;
            cp16(dbB + (uint32_t)(r * 32 + w4) * 4, Bk + (long)r * ldb);
        }
        asm volatile("cp.async.commit_group;" ::: "memory");
    };

    stage_copy(0, 0);
    stage_copy(1, 1);

    int cbuf = 0;
#pragma unroll 1
    for (int it = 0; it < NIT; it++) {
        asm volatile("cp.async.wait_group %0;" :: "n"(NSTAGE - 2) : "memory");
        __syncthreads();
        if (it + 2 < NIT) {
            int nb = cbuf + 2; if (nb >= NSTAGE) nb -= NSTAGE;
            stage_copy(it + 2, nb);
        }

        const uint32_t* sA = smem + cbuf * BUF2_WORDS;
        const uint32_t* sB = sA + AWORDS;

#pragma unroll
        for (int ks = 0; ks < 4; ks++) {
            const int sw0 = ((2 * ks)     ^ grp) * 4 + tg;
            const int sw1 = ((2 * ks + 1) ^ grp) * 4 + tg;
            uint32_t af[4][4];
#pragma unroll
            for (int mt = 0; mt < 4; mt++) {
                const int r0 = (wm + mt * 16 + grp) * 32;
                const int r1 = r0 + 8 * 32;
                af[mt][0] = sA[r0 + sw0];
                af[mt][1] = sA[r1 + sw0];
                af[mt][2] = sA[r0 + sw1];
                af[mt][3] = sA[r1 + sw1];
            }
            uint32_t bf[4][2];
#pragma unroll
            for (int nt = 0; nt < 4; nt++) {
                const int rb = (wn + nt * 8 + grp) * 32;
                bf[nt][0] = sB[rb + sw0];
                bf[nt][1] = sB[rb + sw1];
            }
#pragma unroll
            for (int mt = 0; mt < 4; mt++)
#pragma unroll
                for (int nt = 0; nt < 4; nt++)
                    mma_f16(acc[mt][nt][0], acc[mt][nt][1], acc[mt][nt][2], acc[mt][nt][3],
                            af[mt][0], af[mt][1], af[mt][2], af[mt][3],
                            bf[nt][0], bf[nt][1]);
        }
        cbuf++; if (cbuf >= NSTAGE) cbuf = 0;
    }

    // ---- epilogue ----
    if (MODE == 1) {
        __half* Ch = (__half*)Cv;
        const int ct = (int)((bn + wn) >> 5);
#pragma unroll
        for (int mt = 0; mt < 4; mt++) {
            const long r0 = bm + wm + mt * 16 + grp;
            float rs0 = 0.0f, rs1 = 0.0f;
#pragma unroll
            for (int nt = 0; nt < 4; nt++) {
                const int cn = (int)bn + wn + nt * 8 + 2 * tg;
                const float e00 = __expf(acc[mt][nt][0] * alpha);
                const float e01 = __expf(acc[mt][nt][1] * alpha);
                const float e10 = __expf(acc[mt][nt][2] * alpha);
                const float e11 = __expf(acc[mt][nt][3] * alpha);
                const __half2 h0 = __floats2half2_rn(e00, e01);
                const __half2 h1 = __floats2half2_rn(e10, e11);
                const float2 b0 = __half22float2(h0);
                const float2 b1 = __half22float2(h1);
                rs0 += b0.x + b0.y;
                rs1 += b1.x + b1.y;
                *reinterpret_cast<__half2*>(Ch + r0 * (long)ldc + cn)       = h0;
                *reinterpret_cast<__half2*>(Ch + (r0 + 8) * (long)ldc + cn) = h1;
            }
            rs0 += __shfl_xor_sync(0xffffffffu, rs0, 1);
            rs0 += __shfl_xor_sync(0xffffffffu, rs0, 2);
            rs1 += __shfl_xor_sync(0xffffffffu, rs1, 1);
            rs1 += __shfl_xor_sync(0xffffffffu, rs1, 2);
            if (tg == 0) {
                aux[(size_t)r0 * PS + ct]       = rs0;
                aux[(size_t)(r0 + 8) * PS + ct] = rs1;
            }
        }
    } else if (MODE == 3) {
        __half* Ch = (__half*)Cv;
#pragma unroll
        for (int mt = 0; mt < 4; mt++) {
            const long r0 = bm + wm + mt * 16 + grp;
#pragma unroll
            for (int nt = 0; nt < 4; nt++) {
                const int cn = (int)bn + wn + nt * 8 + 2 * tg;
                float v00 = acc[mt][nt][0] * alpha;
                float v01 = acc[mt][nt][1] * alpha;
                float v10 = acc[mt][nt][2] * alpha;
                float v11 = acc[mt][nt][3] * alpha;
                if (HASBIAS) {
                    const float b0 = bias[cn], b1 = bias[cn + 1];
                    v00 += b0; v01 += b1;
                    v10 += b0; v11 += b1;
                }
                Ch[(size_t)cn * ldc + r0]           = __float2half_rn(v00);
                Ch[(size_t)(cn + 1) * ldc + r0]     = __float2half_rn(v01);
                Ch[(size_t)cn * ldc + r0 + 8]       = __float2half_rn(v10);
                Ch[(size_t)(cn + 1) * ldc + r0 + 8] = __float2half_rn(v11);
            }
        }
    } else {
#pragma unroll
        for (int mt = 0; mt < 4; mt++) {
            const long r0 = bm + wm + mt * 16 + grp;
#pragma unroll
            for (int nt = 0; nt < 4; nt++) {
                const int cn = (int)bn + wn + nt * 8 + 2 * tg;
                float v00 = acc[mt][nt][0] * alpha;
                float v01 = acc[mt][nt][1] * alpha;
                float v10 = acc[mt][nt][2] * alpha;
                float v11 = acc[mt][nt][3] * alpha;
                if (HASBIAS) {
                    const float b0 = bias[cn], b1 = bias[cn + 1];
                    v00 += b0; v01 += b1;
                    v10 += b0; v11 += b1;
                }
                if (OUTHALF) {
                    __half* Ch = (__half*)Cv;
                    *reinterpret_cast<__half2*>(Ch + r0 * (long)ldc + cn)       = __floats2half2_rn(v00, v01);
                    *reinterpret_cast<__half2*>(Ch + (r0 + 8) * (long)ldc + cn) = __floats2half2_rn(v10, v11);
                } else {
                    float* Cf = (float*)Cv;
                    *reinterpret_cast<float2*>(Cf + r0 * (long)ldc + cn)       = make_float2(v00, v01);
                    *reinterpret_cast<float2*>(Cf + (r0 + 8) * (long)ldc + cn) = make_float2(v10, v11);
                }
            }
        }
    }
}

// ---------------------------------------------------------------------------
__global__ void __launch_bounds__(256) f2h_kernel(const float* __restrict__ q,
                                                  const float* __restrict__ k,
                                                  const float* __restrict__ v)
{
    const int z = blockIdx.y;
    const float* src = z == 0 ? q : z == 1 ? k : v;
    __half* dst = z == 0 ? g_qin : z == 1 ? g_kin : g_vin;
    const size_t i = (size_t)blockIdx.x * 256 + threadIdx.x;
    const float4 val = reinterpret_cast<const float4*>(src)[i];
    __half2 h0 = __floats2half2_rn(val.x, val.y);
    __half2 h1 = __floats2half2_rn(val.z, val.w);
    uint2 o;
    o.x = *reinterpret_cast<uint32_t*>(&h0);
    o.y = *reinterpret_cast<uint32_t*>(&h1);
    reinterpret_cast<uint2*>(dst)[i] = o;
}

__global__ void __launch_bounds__(256) transw_kernel(
    const float* __restrict__ Wq, const float* __restrict__ Wk,
    const float* __restrict__ Wv, const float* __restrict__ Wo)
{
    __shared__ float t[32][33];
    const int z = blockIdx.z;
    const float* src;
    __half* dst;
    int R, C;
    if (z == 12) { src = Wo; dst = g_WoTh; R = DM; C = DM; }
    else {
        const int mat = z >> 2, head = z & 3;
        const float* W = mat == 0 ? Wq : mat == 1 ? Wk : Wv;
        src = W + (size_t)head * DM * DK;
        dst = g_WTh + (size_t)z * DK * DM;
        R = DM; C = DK;
        if (blockIdx.x >= 8) return;
    }

    const int c0 = blockIdx.x * 32, r0 = blockIdx.y * 32;
    const int tx = threadIdx.x & 31, ty = threadIdx.x >> 5;
#pragma unroll
    for (int i = 0; i < 4; i++)
        t[ty + i * 8][tx] = src[(size_t)(r0 + ty + i * 8) * C + c0 + tx];
    __syncthreads();
#pragma unroll
    for (int i = 0; i < 4; i++)
        dst[(size_t)(c0 + ty + i * 8) * R + r0 + tx] = __float2half_rn(t[tx][ty + i * 8]);
}

__global__ void __launch_bounds__(256) invsum_kernel()
{
    const int row  = blockIdx.x * 8 + (threadIdx.x >> 5);
    const int lane = threadIdx.x & 31;
    const float* p = g_psum + (size_t)row * PS;
    float s = p[lane] + p[lane + 32] + p[lane + 64] + p[lane + 96];
#pragma unroll
    for (int o = 16; o > 0; o >>= 1) s += __shfl_xor_sync(0xffffffffu, s, o);
    if (lane == 0) g_invsum[row] = 1.0f / s;
}

__global__ void __launch_bounds__(256) hored_kernel()
{
    const size_t n2 = (size_t)BS_TOT * DM / 2;
    const size_t i  = (size_t)blockIdx.x * 256 + threadIdx.x;
    const __half2* p = reinterpret_cast<const __half2*>(g_HOp);
    float2 s = __half22float2(p[i]);
    float2 a1 = __half22float2(p[i + n2]);
    float2 a2 = __half22float2(p[i + 2 * n2]);
    float2 a3 = __half22float2(p[i + 3 * n2]);
    s.x += a1.x + a2.x + a3.x;
    s.y += a1.y + a2.y + a3.y;
    reinterpret_cast<__half2*>(g_HOh)[i] = __floats2half2_rn(s.x, s.y);
}

// ---------------------------------------------------------------------------
// proj (gemm_h2): grid (2, 64, 12); V written transposed into g_VTh
// ---------------------------------------------------------------------------
__global__ void __launch_bounds__(256, 2) proj_tc(
    const float* __restrict__ bq, const float* __restrict__ bk, const float* __restrict__ bv)
{
    const int z = blockIdx.z, mat = z >> 2, head = z & 3;
    const __half* A    = mat == 0 ? g_qin : mat == 1 ? g_kin : g_vin;
    const __half* B    = g_WTh + (size_t)z * DK * DM;
    const float*  bias = (mat == 0 ? bq : mat == 1 ? bk : bv) + head * DK;
    if (mat == 2) {
        __half* C = g_VTh + (size_t)head * BS_TOT * DK;
        const long b = (long)blockIdx.y / 32;
        __half* Cb = C + b * SEQ * DK - b * SEQ;
        gemm_h2<true, true, 3>(A, DM, B, DM, Cb, SEQ, DM, 1.0f, bias, nullptr);
    } else {
        __half* C = (mat == 0 ? g_Qh : g_Kh) + (size_t)head * BS_TOT * DK;
        gemm_h2<true, true, 0>(A, DM, B, DM, C, DK, DM, 1.0f, bias, nullptr);
    }
}

__global__ void __launch_bounds__(256, 2) scores_tc()
{
    const int z = blockIdx.z;
    gemm_h2<false, true, 1>(g_Qh + (size_t)z * SEQ * DK, DK,
                            g_Kh + (size_t)z * SEQ * DK, DK,
                            g_Eh + (size_t)z * SEQ * SEQ, SEQ, DK, 0.0625f,
                            nullptr, g_psum + (size_t)z * SEQ * PS);
}

// av split-K4 (gemm_h 64x64 path)
__global__ void __launch_bounds__(256, 1) av_tc(float* __restrict__ attn_out)
{
    float* attn = attn_out ? attn_out : g_attn_fallback;
    const int z = blockIdx.z, h = z >> 1, b = z & 1;
    const int slab = blockIdx.x;
    const __half* A = g_Eh + (size_t)z * SEQ * SEQ + (size_t)slab * KSLAB;
    const __half* B = g_VTh + (size_t)z * DK * SEQ + (size_t)slab * KSLAB;
    __half* C = g_HOp + (size_t)slab * BS_TOT * DM + (size_t)b * SEQ * DM + h * DK;
    float* aux = attn + (size_t)z * SEQ * SEQ + (size_t)slab * KSLAB;
    gemm_h<2, 4, false, true, 2, true>(A, SEQ, B, SEQ, C, DM, KSLAB, 1.0f,
                                       nullptr, aux, g_invsum + (size_t)z * SEQ);
}

__global__ void __launch_bounds__(256, 2) outproj_tc(const float* __restrict__ bo,
                                                     float* __restrict__ out)
{
    gemm_h2<true, false, 0>(g_HOh, DM, g_WoTh, DM, out, DM, DM, 1.0f, bo, nullptr);
}

// ---------------------------------------------------------------------------
extern "C" void kernel_launch(void* const* d_in, const int* in_sizes, int n_in,
                              void* d_out, int out_size)
{
    const float* q  = (const float*)d_in[0];
    const float* k  = (const float*)d_in[1];
    const float* v  = (const float*)d_in[2];
    const float* Wq = (const float*)d_in[3];
    const float* bq = (const float*)d_in[4];
    const float* Wk = (const float*)d_in[5];
    const float* bk = (const float*)d_in[6];
    const float* Wv = (const float*)d_in[7];
    const float* bv = (const float*)d_in[8];
    const float* Wo = (const float*)d_in[9];
    const float* bo = (const float*)d_in[10];

    float* out = (float*)d_out;
    const long OUT_ELEMS  = (long)NB * SEQ * DM;
    const long ATTN_ELEMS = (long)NH * NB * SEQ * SEQ;
    float* attn_out = nullptr;
    if ((long)out_size >= OUT_ELEMS + ATTN_ELEMS) attn_out = out + OUT_ELEMS;

    cudaFuncSetAttribute(proj_tc,    cudaFuncAttributeMaxDynamicSharedMemorySize, SMEM2_BYTES);
    cudaFuncSetAttribute(scores_tc,  cudaFuncAttributeMaxDynamicSharedMemorySize, SMEM2_BYTES);
    cudaFuncSetAttribute(av_tc,      cudaFuncAttributeMaxDynamicSharedMemorySize, SMEM_BYTES);
    cudaFuncSetAttribute(outproj_tc, cudaFuncAttributeMaxDynamicSharedMemorySize, SMEM2_BYTES);

    f2h_kernel<<<dim3(BS_TOT * DM / 4 / 256, 3), 256>>>(q, k, v);

    transw_kernel<<<dim3(32, 32, 13), 256>>>(Wq, Wk, Wv, Wo);

    // proj: 128x128 tiles, 2 CTAs/SM
    proj_tc<<<dim3(2, 64, 12), 256, SMEM2_BYTES>>>(bq, bk, bv);

    // scores: 128x128 tiles, 2 CTAs/SM
    scores_tc<<<dim3(32, 32, 8), 256, SMEM2_BYTES>>>();

    invsum_kernel<<<dim3(NROWS / 8), 256>>>();

    // av: split-K4 (64x64 path) -> fp16 HO partials + normalized attn
    av_tc<<<dim3(KSLABS, 32, 8), 256, SMEM_BYTES>>>(attn_out);

    hored_kernel<<<dim3(BS_TOT * DM / 2 / 256), 256>>>();

    // outproj: 128x128 tiles, 2 CTAs/SM
    outproj_tc<<<dim3(8, 64, 1), 256, SMEM2_BYTES>>>(bo, out);
}

// round 16
// speedup vs baseline: 1.1147x; 1.0198x over previous
#include <cuda_runtime.h>
#include <cuda_fp16.h>
#include <cstdint>
#include <math.h>

// ---------------------------------------------------------------------------
// LegalMultiHeadAttention — Round 16: 2-CTA/SM everywhere.
//   gemm_h2 (128x128 CTA, 64x32 warp tile) for proj/scores/outproj;
//   gemm_av2 (64x256 CTA, 32x64 warp tile, 32-K stages) for av split-K4
//   with MODE-2 attn writeback (full-N CTA => each E staged once).
// fp16 m16n8k16, 3-stage cp.async, fused softmax scheme.
//   B=2, S=4096, D_MODEL=1024, H=4, D_K=256.
// ---------------------------------------------------------------------------

#define SEQ    4096
#define DK     256
#define DM     1024
#define NH     4
#define NB     2
#define BS_TOT (NB*SEQ)          // 8192
#define NROWS  (NH*NB*SEEQ_DUMMY)
#undef NROWS
#define NROWS  (NH*NB*SEQ)       // 32768
#define KSLABS 4
#define KSLAB  (SEQ/KSLABS)      // 1024
#define PS     128               // psum slots per row (32-col granularity)

__device__ __half g_qin[(size_t)BS_TOT*DM];
__device__ __half g_kin[(size_t)BS_TOT*DM];
__device__ __half g_vin[(size_t)BS_TOT*DM];
__device__ __half g_Qh [(size_t)NH*BS_TOT*DK];
__device__ __half g_Kh [(size_t)NH*BS_TOT*DK];
__device__ __half g_VTh[(size_t)NH*BS_TOT*DK];    // [z][DK][SEQ], written by proj
__device__ __half g_HOh[(size_t)BS_TOT*DM];
__device__ __half g_HOp[(size_t)KSLABS*BS_TOT*DM]; // split-K partial HO
__device__ __half g_WTh[(size_t)3*NH*DK*DM];
__device__ __half g_WoTh[(size_t)DM*DM];
__device__ __half g_Eh [(size_t)NH*NB*SEQ*SEQ];   // unnormalized exp
__device__ float  g_psum[(size_t)NROWS*PS];
__device__ float  g_invsum[NROWS];
__device__ float  g_attn_fallback[(size_t)NH*NB*SEQ*SEQ];

__device__ __forceinline__ uint32_t smem_u32(const void* p) {
    uint32_t a;
    asm("{ .reg .u64 t; cvta.to.shared.u64 t, %1; cvt.u32.u64 %0, t; }"
        : "=r"(a) : "l"(p));
    return a;
}
__device__ __forceinline__ void mma_f16(float& c0, float& c1, float& c2, float& c3,
                                        uint32_t a0, uint32_t a1, uint32_t a2, uint32_t a3,
                                        uint32_t b0, uint32_t b1) {
    asm volatile(
        "mma.sync.aligned.m16n8k16.row.col.f32.f16.f16.f32 "
        "{%0,%1,%2,%3}, {%4,%5,%6,%7}, {%8,%9}, {%0,%1,%2,%3};"
        : "+f"(c0), "+f"(c1), "+f"(c2), "+f"(c3)
        : "r"(a0), "r"(a1), "r"(a2), "r"(a3), "r"(b0), "r"(b1));
}
__device__ __forceinline__ void cp16(uint32_t dst, const void* src) {
    asm volatile("cp.async.cg.shared.global [%0], [%1], 16;" :: "r"(dst), "l"(src));
}

#define NSTAGE 3
// h2 path (128x128 CTA, 64-K stages): 256 rows * 32 words
#define BUF2_WORDS 8192
#define SMEM2_BYTES (NSTAGE*BUF2_WORDS*4)    // 98304
// av2 path (64x256 CTA, 32-K stages): 320 rows * 16 words
#define BUFA_WORDS 5120
#define SMEMA_BYTES (NSTAGE*BUFA_WORDS*4)    // 61440

// ---------------------------------------------------------------------------
// gemm_h2: CTA 128x128, 8 warps 2(M) x 4(N), warp tile 64x32, <=128 regs,
// 64-K stages, chunk-XOR swizzle (32-word rows). 2 CTAs/SM.
// MODE 0 plain | 1 scores (exp + 32-col psum) | 3 transposed fp16 store.
// ---------------------------------------------------------------------------
template<bool HASBIAS, bool OUTHALF, int MODE>
__device__ __forceinline__ void gemm_h2(const __half* __restrict__ A, int lda,
                                        const __half* __restrict__ B, int ldb,
                                        void* __restrict__ Cv, int ldc,
                                        int K, float alpha, const float* __restrict__ bias,
                                        float* __restrict__ aux)
{
    extern __shared__ uint32_t smem[];
    const uint32_t sbase = smem_u32(smem);

    const int tid  = threadIdx.x;           // 256
    const int wid  = tid >> 5;
    const int lane = tid & 31;
    const int grp  = lane >> 2;
    const int tg   = lane & 3;
    const int wm   = (wid >> 2) * 64;        // 0,64
    const int wn   = (wid & 3) * 32;         // 0,32,64,96

    const long bm = (long)blockIdx.y * 128;
    const long bn = (long)blockIdx.x * 128;
    A += bm * (long)lda;
    B += bn * (long)ldb;

    const int sm8 = tid >> 3;
    const int skc = tid & 7;
    const int w4  = (skc ^ (sm8 & 7)) * 4;

    float acc[4][4][4];
#pragma unroll
    for (int i = 0; i < 4; i++)
#pragma unroll
        for (int j = 0; j < 4; j++)
#pragma unroll
            for (int r = 0; r < 4; r++) acc[i][j][r] = 0.0f;

    const int NIT = K >> 6;
    const int AWORDS = 128 * 32;

    auto stage_copy = [&](int stage, int buf) {
        const uint32_t db = sbase + (uint32_t)buf * (BUF2_WORDS * 4);
        const __half* Ak = A + stage * 64 + skc * 8;
        const __half* Bk = B + stage * 64 + skc * 8;
#pragma unroll
        for (int c = 0; c < 4; c++) {
            const int r = sm8 + c * 32;
            cp16(db + (uint32_t)(r * 32 + w4) * 4, Ak + (long)r * lda);
        }
        const uint32_t dbB = db + (uint32_t)AWORDS * 4;
#pragma unroll
        for (int c = 0; c < 4; c++) {
            const int r = sm8 + c * 32;
            cp16(dbB + (uint32_t)(r * 32 + w4) * 4, Bk + (long)r * ldb);
        }
        asm volatile("cp.async.commit_group;" ::: "memory");
    };

    stage_copy(0, 0);
    stage_copy(1, 1);

    int cbuf = 0;
#pragma unroll 1
    for (int it = 0; it < NIT; it++) {
        asm volatile("cp.async.wait_group %0;" :: "n"(NSTAGE - 2) : "memory");
        __syncthreads();
        if (it + 2 < NIT) {
            int nb = cbuf + 2; if (nb >= NSTAGE) nb -= NSTAGE;
            stage_copy(it + 2, nb);
        }

        const uint32_t* sA = smem + cbuf * BUF2_WORDS;
        const uint32_t* sB = sA + AWORDS;

#pragma unroll
        for (int ks = 0; ks < 4; ks++) {
            const int sw0 = ((2 * ks)     ^ grp) * 4 + tg;
            const int sw1 = ((2 * ks + 1) ^ grp) * 4 + tg;
            uint32_t af[4][4];
#pragma unroll
            for (int mt = 0; mt < 4; mt++) {
                const int r0 = (wm + mt * 16 + grp) * 32;
                const int r1 = r0 + 8 * 32;
                af[mt][0] = sA[r0 + sw0];
                af[mt][1] = sA[r1 + sw0];
                af[mt][2] = sA[r0 + sw1];
                af[mt][3] = sA[r1 + sw1];
            }
            uint32_t bf[4][2];
#pragma unroll
            for (int nt = 0; nt < 4; nt++) {
                const int rb = (wn + nt * 8 + grp) * 32;
                bf[nt][0] = sB[rb + sw0];
                bf[nt][1] = sB[rb + sw1];
            }
#pragma unroll
            for (int mt = 0; mt < 4; mt++)
#pragma unroll
                for (int nt = 0; nt < 4; nt++)
                    mma_f16(acc[mt][nt][0], acc[mt][nt][1], acc[mt][nt][2], acc[mt][nt][3],
                            af[mt][0], af[mt][1], af[mt][2], af[mt][3],
                            bf[nt][0], bf[nt][1]);
        }
        cbuf++; if (cbuf >= NSTAGE) cbuf = 0;
    }

    // ---- epilogue ----
    if (MODE == 1) {
        __half* Ch = (__half*)Cv;
        const int ct = (int)((bn + wn) >> 5);
#pragma unroll
        for (int mt = 0; mt < 4; mt++) {
            const long r0 = bm + wm + mt * 16 + grp;
            float rs0 = 0.0f, rs1 = 0.0f;
#pragma unroll
            for (int nt = 0; nt < 4; nt++) {
                const int cn = (int)bn + wn + nt * 8 + 2 * tg;
                const float e00 = __expf(acc[mt][nt][0] * alpha);
                const float e01 = __expf(acc[mt][nt][1] * alpha);
                const float e10 = __expf(acc[mt][nt][2] * alpha);
                const float e11 = __expf(acc[mt][nt][3] * alpha);
                const __half2 h0 = __floats2half2_rn(e00, e01);
                const __half2 h1 = __floats2half2_rn(e10, e11);
                const float2 b0 = __half22float2(h0);
                const float2 b1 = __half22float2(h1);
                rs0 += b0.x + b0.y;
                rs1 += b1.x + b1.y;
                *reinterpret_cast<__half2*>(Ch + r0 * (long)ldc + cn)       = h0;
                *reinterpret_cast<__half2*>(Ch + (r0 + 8) * (long)ldc + cn) = h1;
            }
            rs0 += __shfl_xor_sync(0xffffffffu, rs0, 1);
            rs0 += __shfl_xor_sync(0xffffffffu, rs0, 2);
            rs1 += __shfl_xor_sync(0xffffffffu, rs1, 1);
            rs1 += __shfl_xor_sync(0xffffffffu, rs1, 2);
            if (tg == 0) {
                aux[(size_t)r0 * PS + ct]       = rs0;
                aux[(size_t)(r0 + 8) * PS + ct] = rs1;
            }
        }
    } else if (MODE == 3) {
        __half* Ch = (__half*)Cv;
#pragma unroll
        for (int mt = 0; mt < 4; mt++) {
            const long r0 = bm + wm + mt * 16 + grp;
#pragma unroll
            for (int nt = 0; nt < 4; nt++) {
                const int cn = (int)bn + wn + nt * 8 + 2 * tg;
                float v00 = acc[mt][nt][0] * alpha;
                float v01 = acc[mt][nt][1] * alpha;
                float v10 = acc[mt][nt][2] * alpha;
                float v11 = acc[mt][nt][3] * alpha;
                if (HASBIAS) {
                    const float b0 = bias[cn], b1 = bias[cn + 1];
                    v00 += b0; v01 += b1;
                    v10 += b0; v11 += b1;
                }
                Ch[(size_t)cn * ldc + r0]           = __float2half_rn(v00);
                Ch[(size_t)(cn + 1) * ldc + r0]     = __float2half_rn(v01);
                Ch[(size_t)cn * ldc + r0 + 8]       = __float2half_rn(v10);
                Ch[(size_t)(cn + 1) * ldc + r0 + 8] = __float2half_rn(v11);
            }
        }
    } else {
#pragma unroll
        for (int mt = 0; mt < 4; mt++) {
            const long r0 = bm + wm + mt * 16 + grp;
#pragma unroll
            for (int nt = 0; nt < 4; nt++) {
                const int cn = (int)bn + wn + nt * 8 + 2 * tg;
                float v00 = acc[mt][nt][0] * alpha;
                float v01 = acc[mt][nt][1] * alpha;
                float v10 = acc[mt][nt][2] * alpha;
                float v11 = acc[mt][nt][3] * alpha;
                if (HASBIAS) {
                    const float b0 = bias[cn], b1 = bias[cn + 1];
                    v00 += b0; v01 += b1;
                    v10 += b0; v11 += b1;
                }
                if (OUTHALF) {
                    __half* Ch = (__half*)Cv;
                    *reinterpret_cast<__half2*>(Ch + r0 * (long)ldc + cn)       = __floats2half2_rn(v00, v01);
                    *reinterpret_cast<__half2*>(Ch + (r0 + 8) * (long)ldc + cn) = __floats2half2_rn(v10, v11);
                } else {
                    float* Cf = (float*)Cv;
                    *reinterpret_cast<float2*>(Cf + r0 * (long)ldc + cn)       = make_float2(v00, v01);
                    *reinterpret_cast<float2*>(Cf + (r0 + 8) * (long)ldc + cn) = make_float2(v10, v11);
                }
            }
        }
    }
}

// ---------------------------------------------------------------------------
// gemm_av2: CTA 64x256, 8 warps 2(M) x 4(N), warp tile 32x64, 32-K stages,
// <=128 regs -> 2 CTAs/SM. av only: attn writeback + invrow-scaled fp16 HO.
// smem row = 16 words; chunk c4 swizzled by ((row>>1)&3)<<2 (R9 layout).
// ---------------------------------------------------------------------------
__device__ __forceinline__ void gemm_av2(const __half* __restrict__ A, int lda,
                                         const __half* __restrict__ B, int ldb,
                                         __half* __restrict__ C, int ldc,
                                         int K,
                                         float* __restrict__ aux,
                                         const float* __restrict__ invrow)
{
    extern __shared__ uint32_t smem[];
    const uint32_t sbase = smem_u32(smem);

    const int tid  = threadIdx.x;           // 256
    const int wid  = tid >> 5;
    const int lane = tid & 31;
    const int grp  = lane >> 2;
    const int tg   = lane & 3;
    const int wm   = (wid >> 2) * 32;        // 0,32
    const int wn   = (wid & 3) * 64;         // 0,64,128,192

    const long bm = (long)blockIdx.y * 64;
    A += bm * (long)lda;

    const int sm4 = tid >> 2;                // 0..63
    const int c4  = tid & 3;                 // 16B chunk

    const float invs = invrow[bm + sm4];     // for writeback of row sm4

    float acc[2][8][4];
#pragma unroll
    for (int i = 0; i < 2; i++)
#pragma unroll
        for (int j = 0; j < 8; j++)
#pragma unroll
            for (int r = 0; r < 4; r++) acc[i][j][r] = 0.0f;

    const int NIT = K >> 5;
    const int AWORDS = 64 * 16;              // 1024

    auto stage_copy = [&](int stage, int buf) {
        const uint32_t db = sbase + (uint32_t)buf * (BUFA_WORDS * 4);
        const __half* Ak = A + stage * 32 + c4 * 8;
        const __half* Bk = B + stage * 32 + c4 * 8;
        {   // A: 64 rows, 1 chunk per thread
            const int r = sm4;
            const int w = r * 16 + ((c4 * 4) ^ (((r >> 1) & 3) << 2));
            cp16(db + (uint32_t)w * 4, Ak + (long)r * lda);
        }
        const uint32_t dbB = db + (uint32_t)AWORDS * 4;
#pragma unroll
        for (int c = 0; c < 4; c++) {        // B: 256 rows
            const int r = sm4 + c * 64;
            const int w = r * 16 + ((c4 * 4) ^ (((r >> 1) & 3) << 2));
            cp16(dbB + (uint32_t)w * 4, Bk + (long)r * ldb);
        }
        asm volatile("cp.async.commit_group;" ::: "memory");
    };

    stage_copy(0, 0);
    stage_copy(1, 1);

    int cbuf = 0;
#pragma unroll 1
    for (int it = 0; it < NIT; it++) {
        asm volatile("cp.async.wait_group %0;" :: "n"(NSTAGE - 2) : "memory");
        __syncthreads();
        if (it + 2 < NIT) {
            int nb = cbuf + 2; if (nb >= NSTAGE) nb -= NSTAGE;
            stage_copy(it + 2, nb);
        }

        const uint32_t* sA = smem + cbuf * BUFA_WORDS;
        const uint32_t* sB = sA + AWORDS;

        // writeback: normalized fp32 attn (each E element staged once)
        {
            const int m = sm4;
            const int w = m * 16 + ((c4 * 4) ^ (((m >> 1) & 3) << 2));
            const uint4 d = *reinterpret_cast<const uint4*>(sA + w);
            float2 f0 = __half22float2(*reinterpret_cast<const __half2*>(&d.x));
            float2 f1 = __half22float2(*reinterpret_cast<const __half2*>(&d.y));
            float2 f2 = __half22float2(*reinterpret_cast<const __half2*>(&d.z));
            float2 f3 = __half22float2(*reinterpret_cast<const __half2*>(&d.w));
            float4 o0 = make_float4(f0.x * invs, f0.y * invs, f1.x * invs, f1.y * invs);
            float4 o1 = make_float4(f2.x * invs, f2.y * invs, f3.x * invs, f3.y * invs);
            float* dst = aux + (bm + m) * (long)lda + it * 32 + c4 * 8;
            *reinterpret_cast<float4*>(dst)     = o0;
            *reinterpret_cast<float4*>(dst + 4) = o1;
        }

#pragma unroll
        for (int ks = 0; ks < 2; ks++) {
            const int kb = ks * 8;
            uint32_t af[2][4];
#pragma unroll
            for (int mt = 0; mt < 2; mt++) {
                const int r0 = wm + mt * 16 + grp;
                const int r1 = r0 + 8;
                const int s0 = ((r0 >> 1) & 3) << 2;
                const int s1 = ((r1 >> 1) & 3) << 2;
                af[mt][0] = sA[r0 * 16 + ((kb + tg)     ^ s0)];
                af[mt][1] = sA[r1 * 16 + ((kb + tg)     ^ s1)];
                af[mt][2] = sA[r0 * 16 + ((kb + tg + 4) ^ s0)];
                af[mt][3] = sA[r1 * 16 + ((kb + tg + 4) ^ s1)];
            }
            uint32_t bf[8][2];
#pragma unroll
            for (int nt = 0; nt < 8; nt++) {
                const int rb = wn + nt * 8 + grp;
                const int sb = ((rb >> 1) & 3) << 2;
                bf[nt][0] = sB[rb * 16 + ((kb + tg)     ^ sb)];
                bf[nt][1] = sB[rb * 16 + ((kb + tg + 4) ^ sb)];
            }
#pragma unroll
            for (int mt = 0; mt < 2; mt++)
#pragma unroll
                for (int nt = 0; nt < 8; nt++)
                    mma_f16(acc[mt][nt][0], acc[mt][nt][1], acc[mt][nt][2], acc[mt][nt][3],
                            af[mt][0], af[mt][1], af[mt][2], af[mt][3],
                            bf[nt][0], bf[nt][1]);
        }
        cbuf++; if (cbuf >= NSTAGE) cbuf = 0;
    }

    // epilogue: invrow-scaled fp16 HO partial
#pragma unroll
    for (int mt = 0; mt < 2; mt++) {
        const long r0 = bm + wm + mt * 16 + grp;
        const float s0 = invrow[r0];
        const float s1 = invrow[r0 + 8];
#pragma unroll
        for (int nt = 0; nt < 8; nt++) {
            const int cn = wn + nt * 8 + 2 * tg;
            *reinterpret_cast<__half2*>(C + r0 * (long)ldc + cn) =
                __floats2half2_rn(acc[mt][nt][0] * s0, acc[mt][nt][1] * s0);
            *reinterpret_cast<__half2*>(C + (r0 + 8) * (long)ldc + cn) =
                __floats2half2_rn(acc[mt][nt][2] * s1, acc[mt][nt][3] * s1);
        }
    }
}

// ---------------------------------------------------------------------------
__global__ void __launch_bounds__(256) f2h_kernel(const float* __restrict__ q,
                                                  const float* __restrict__ k,
                                                  const float* __restrict__ v)
{
    const int z = blockIdx.y;
    const float* src = z == 0 ? q : z == 1 ? k : v;
    __half* dst = z == 0 ? g_qin : z == 1 ? g_kin : g_vin;
    const size_t i = (size_t)blockIdx.x * 256 + threadIdx.x;
    const float4 val = reinterpret_cast<const float4*>(src)[i];
    __half2 h0 = __floats2half2_rn(val.x, val.y);
    __half2 h1 = __floats2half2_rn(val.z, val.w);
    uint2 o;
    o.x = *reinterpret_cast<uint32_t*>(&h0);
    o.y = *reinterpret_cast<uint32_t*>(&h1);
    reinterpret_cast<uint2*>(dst)[i] = o;
}

__global__ void __launch_bounds__(256) transw_kernel(
    const float* __restrict__ Wq, const float* __restrict__ Wk,
    const float* __restrict__ Wv, const float* __restrict__ Wo)
{
    __shared__ float t[32][33];
    const int z = blockIdx.z;
    const float* src;
    __half* dst;
    int R, C;
    if (z == 12) { src = Wo; dst = g_WoTh; R = DM; C = DM; }
    else {
        const int mat = z >> 2, head = z & 3;
        const float* W = mat == 0 ? Wq : mat == 1 ? Wk : Wv;
        src = W + (size_t)head * DM * DK;
        dst = g_WTh + (size_t)z * DK * DM;
        R = DM; C = DK;
        if (blockIdx.x >= 8) return;
    }

    const int c0 = blockIdx.x * 32, r0 = blockIdx.y * 32;
    const int tx = threadIdx.x & 31, ty = threadIdx.x >> 5;
#pragma unroll
    for (int i = 0; i < 4; i++)
        t[ty + i * 8][tx] = src[(size_t)(r0 + ty + i * 8) * C + c0 + tx];
    __syncthreads();
#pragma unroll
    for (int i = 0; i < 4; i++)
        dst[(size_t)(c0 + ty + i * 8) * R + r0 + tx] = __float2half_rn(t[tx][ty + i * 8]);
}

__global__ void __launch_bounds__(256) invsum_kernel()
{
    const int row  = blockIdx.x * 8 + (threadIdx.x >> 5);
    const int lane = threadIdx.x & 31;
    const float* p = g_psum + (size_t)row * PS;
    float s = p[lane] + p[lane + 32] + p[lane + 64] + p[lane + 96];
#pragma unroll
    for (int o = 16; o > 0; o >>= 1) s += __shfl_xor_sync(0xffffffffu, s, o);
    if (lane == 0) g_invsum[row] = 1.0f / s;
}

__global__ void __launch_bounds__(256) hored_kernel()
{
    const size_t n2 = (size_t)BS_TOT * DM / 2;
    const size_t i  = (size_t)blockIdx.x * 256 + threadIdx.x;
    const __half2* p = reinterpret_cast<const __half2*>(g_HOp);
    float2 s = __half22float2(p[i]);
    float2 a1 = __half22float2(p[i + n2]);
    float2 a2 = __half22float2(p[i + 2 * n2]);
    float2 a3 = __half22float2(p[i + 3 * n2]);
    s.x += a1.x + a2.x + a3.x;
    s.y += a1.y + a2.y + a3.y;
    reinterpret_cast<__half2*>(g_HOh)[i] = __floats2half2_rn(s.x, s.y);
}

// ---------------------------------------------------------------------------
__global__ void __launch_bounds__(256, 2) proj_tc(
    const float* __restrict__ bq, const float* __restrict__ bk, const float* __restrict__ bv)
{
    const int z = blockIdx.z, mat = z >> 2, head = z & 3;
    const __half* A    = mat == 0 ? g_qin : mat == 1 ? g_kin : g_vin;
    const __half* B    = g_WTh + (size_t)z * DK * DM;
    const float*  bias = (mat == 0 ? bq : mat == 1 ? bk : bv) + head * DK;
    if (mat == 2) {
        __half* C = g_VTh + (size_t)head * BS_TOT * DK;
        const long b = (long)blockIdx.y / 32;
        __half* Cb = C + b * SEQ * DK - b * SEQ;
        gemm_h2<true, true, 3>(A, DM, B, DM, Cb, SEQ, DM, 1.0f, bias, nullptr);
    } else {
        __half* C = (mat == 0 ? g_Qh : g_Kh) + (size_t)head * BS_TOT * DK;
        gemm_h2<true, true, 0>(A, DM, B, DM, C, DK, DM, 1.0f, bias, nullptr);
    }
}

__global__ void __launch_bounds__(256, 2) scores_tc()
{
    const int z = blockIdx.z;
    gemm_h2<false, true, 1>(g_Qh + (size_t)z * SEQ * DK, DK,
                            g_Kh + (size_t)z * SEQ * DK, DK,
                            g_Eh + (size_t)z * SEQ * SEQ, SEQ, DK, 0.0625f,
                            nullptr, g_psum + (size_t)z * SEQ * PS);
}

// av split-K4: gemm_av2 (64x256 CTA, 2 CTAs/SM)
__global__ void __launch_bounds__(256, 2) av_tc(float* __restrict__ attn_out)
{
    float* attn = attn_out ? attn_out : g_attn_fallback;
    const int z = blockIdx.z, h = z >> 1, b = z & 1;
    const int slab = blockIdx.x;
    const __half* A = g_Eh + (size_t)z * SEQ * SEQ + (size_t)slab * KSLAB;
    const __half* B = g_VTh + (size_t)z * DK * SEQ + (size_t)slab * KSLAB;
    __half* C = g_HOp + (size_t)slab * BS_TOT * DM + (size_t)b * SEQ * DM + h * DK;
    float* aux = attn + (size_t)z * SEQ * SEQ + (size_t)slab * KSLAB;
    gemm_av2(A, SEQ, B, SEQ, C, DM, KSLAB, aux, g_invsum + (size_t)z * SEQ);
}

__global__ void __launch_bounds__(256, 2) outproj_tc(const float* __restrict__ bo,
                                                     float* __restrict__ out)
{
    gemm_h2<true, false, 0>(g_HOh, DM, g_WoTh, DM, out, DM, DM, 1.0f, bo, nullptr);
}

// ---------------------------------------------------------------------------
extern "C" void kernel_launch(void* const* d_in, const int* in_sizes, int n_in,
                              void* d_out, int out_size)
{
    const float* q  = (const float*)d_in[0];
    const float* k  = (const float*)d_in[1];
    const float* v  = (const float*)d_in[2];
    const float* Wq = (const float*)d_in[3];
    const float* bq = (const float*)d_in[4];
    const float* Wk = (const float*)d_in[5];
    const float* bk = (const float*)d_in[6];
    const float* Wv = (const float*)d_in[7];
    const float* bv = (const float*)d_in[8];
    const float* Wo = (const float*)d_in[9];
    const float* bo = (const float*)d_in[10];

    float* out = (float*)d_out;
    const long OUT_ELEMS  = (long)NB * SEQ * DM;
    const long ATTN_ELEMS = (long)NH * NB * SEQ * SEQ;
    float* attn_out = nullptr;
    if ((long)out_size >= OUT_ELEMS + ATTN_ELEMS) attn_out = out + OUT_ELEMS;

    cudaFuncSetAttribute(proj_tc,    cudaFuncAttributeMaxDynamicSharedMemorySize, SMEM2_BYTES);
    cudaFuncSetAttribute(scores_tc,  cudaFuncAttributeMaxDynamicSharedMemorySize, SMEM2_BYTES);
    cudaFuncSetAttribute(av_tc,      cudaFuncAttributeMaxDynamicSharedMemorySize, SMEMA_BYTES);
    cudaFuncSetAttribute(outproj_tc, cudaFuncAttributeMaxDynamicSharedMemorySize, SMEM2_BYTES);

    f2h_kernel<<<dim3(BS_TOT * DM / 4 / 256, 3), 256>>>(q, k, v);

    transw_kernel<<<dim3(32, 32, 13), 256>>>(Wq, Wk, Wv, Wo);

    // proj: 128x128 tiles, 2 CTAs/SM
    proj_tc<<<dim3(2, 64, 12), 256, SMEM2_BYTES>>>(bq, bk, bv);

    // scores: 128x128 tiles, 2 CTAs/SM
    scores_tc<<<dim3(32, 32, 8), 256, SMEM2_BYTES>>>();

    invsum_kernel<<<dim3(NROWS / 8), 256>>>();

    // av: split-K4, 64x256 tiles, 2 CTAs/SM
    av_tc<<<dim3(KSLABS, 64, 8), 256, SMEMA_BYTES>>>(attn_out);

    hored_kernel<<<dim3(BS_TOT * DM / 2 / 256), 256>>>();

    // outproj: 128x128 tiles, 2 CTAs/SM
    outproj_tc<<<dim3(8, 64, 1), 256, SMEM2_BYTES>>>(bo, out);
}

// round 17
// speedup vs baseline: 1.1369x; 1.0199x over previous
#include <cuda_runtime.h>
#include <cuda_fp16.h>
#include <cstdint>
#include <math.h>

// ---------------------------------------------------------------------------
// LegalMultiHeadAttention — Round 17: R16 + smem-staged coalesced epilogues
// (MODE 0/1 in gemm_h2, av2 HOp store): scattered per-row ST.32 -> conflict-
// free smem stage -> 16B/lane coalesced STG.
//   B=2, S=4096, D_MODEL=1024, H=4, D_K=256.
// ---------------------------------------------------------------------------

#define SEQ    4096
#define DK     256
#define DM     1024
#define NH     4
#define NB     2
#define BS_TOT (NB*SEQ)          // 8192
#define NROWS  (NH*NB*SEQ)       // 32768
#define KSLABS 4
#define KSLAB  (SEQ/KSLABS)      // 1024
#define PS     128               // psum slots per row

__device__ __half g_qin[(size_t)BS_TOT*DM];
__device__ __half g_kin[(size_t)BS_TOT*DM];
__device__ __half g_vin[(size_t)BS_TOT*DM];
__device__ __half g_Qh [(size_t)NH*BS_TOT*DK];
__device__ __half g_Kh [(size_t)NH*BS_TOT*DK];
__device__ __half g_VTh[(size_t)NH*BS_TOT*DK];
__device__ __half g_HOh[(size_t)BS_TOT*DM];
__device__ __half g_HOp[(size_t)KSLABS*BS_TOT*DM];
__device__ __half g_WTh[(size_t)3*NH*DK*DM];
__device__ __half g_WoTh[(size_t)DM*DM];
__device__ __half g_Eh [(size_t)NH*NB*SEQ*SEQ];
__device__ float  g_psum[(size_t)NROWS*PS];
__device__ float  g_invsum[NROWS];
__device__ float  g_attn_fallback[(size_t)NH*NB*SEQ*SEQ];

__device__ __forceinline__ uint32_t smem_u32(const void* p) {
    uint32_t a;
    asm("{ .reg .u64 t; cvta.to.shared.u64 t, %1; cvt.u32.u64 %0, t; }"
        : "=r"(a) : "l"(p));
    return a;
}
__device__ __forceinline__ void mma_f16(float& c0, float& c1, float& c2, float& c3,
                                        uint32_t a0, uint32_t a1, uint32_t a2, uint32_t a3,
                                        uint32_t b0, uint32_t b1) {
    asm volatile(
        "mma.sync.aligned.m16n8k16.row.col.f32.f16.f16.f32 "
        "{%0,%1,%2,%3}, {%4,%5,%6,%7}, {%8,%9}, {%0,%1,%2,%3};"
        : "+f"(c0), "+f"(c1), "+f"(c2), "+f"(c3)
        : "r"(a0), "r"(a1), "r"(a2), "r"(a3), "r"(b0), "r"(b1));
}
__device__ __forceinline__ void cp16(uint32_t dst, const void* src) {
    asm volatile("cp.async.cg.shared.global [%0], [%1], 16;" :: "r"(dst), "l"(src));
}

#define NSTAGE 3
#define BUF2_WORDS 8192
#define SMEM2_BYTES (NSTAGE*BUF2_WORDS*4)    // 98304 (also covers fp32 stage 67.6KB)
#define BUFA_WORDS 5120
#define SMEMA_BYTES (NSTAGE*BUFA_WORDS*4)    // 61440 (covers av stage 33.8KB)

// ---------------------------------------------------------------------------
// gemm_h2: CTA 128x128, 8 warps 2(M) x 4(N), warp tile 64x32, <=128 regs,
// 64-K stages, chunk-XOR swizzle. 2 CTAs/SM.
// MODE 0 plain | 1 scores (exp + psum) | 3 transposed fp16 store (V^T).
// MODE 0/1 stores are smem-staged for coalescing.
// ---------------------------------------------------------------------------
template<bool HASBIAS, bool OUTHALF, int MODE>
__device__ __forceinline__ void gemm_h2(const __half* __restrict__ A, int lda,
                                        const __half* __restrict__ B, int ldb,
                                        void* __restrict__ Cv, int ldc,
                                        int K, float alpha, const float* __restrict__ bias,
                                        float* __restrict__ aux)
{
    extern __shared__ uint32_t smem[];
    const uint32_t sbase = smem_u32(smem);

    const int tid  = threadIdx.x;           // 256
    const int wid  = tid >> 5;
    const int lane = tid & 31;
    const int grp  = lane >> 2;
    const int tg   = lane & 3;
    const int wm   = (wid >> 2) * 64;
    const int wn   = (wid & 3) * 32;

    const long bm = (long)blockIdx.y * 128;
    const long bn = (long)blockIdx.x * 128;
    A += bm * (long)lda;
    B += bn * (long)ldb;

    const int sm8 = tid >> 3;
    const int skc = tid & 7;
    const int w4  = (skc ^ (sm8 & 7)) * 4;

    float acc[4][4][4];
#pragma unroll
    for (int i = 0; i < 4; i++)
#pragma unroll
        for (int j = 0; j < 4; j++)
#pragma unroll
            for (int r = 0; r < 4; r++) acc[i][j][r] = 0.0f;

    const int NIT = K >> 6;
    const int AWORDS = 128 * 32;

    auto stage_copy = [&](int stage, int buf) {
        const uint32_t db = sbase + (uint32_t)buf * (BUF2_WORDS * 4);
        const __half* Ak = A + stage * 64 + skc * 8;
        const __half* Bk = B + stage * 64 + skc * 8;
#pragma unroll
        for (int c = 0; c < 4; c++) {
            const int r = sm8 + c * 32;
            cp16(db + (uint32_t)(r * 32 + w4) * 4, Ak + (long)r * lda);
        }
        const uint32_t dbB = db + (uint32_t)AWORDS * 4;
#pragma unroll
        for (int c = 0; c < 4; c++) {
            const int r = sm8 + c * 32;
            cp16(dbB + (uint32_t)(r * 32 + w4) * 4, Bk + (long)r * ldb);
        }
        asm volatile("cp.async.commit_group;" ::: "memory");
    };

    stage_copy(0, 0);
    stage_copy(1, 1);

    int cbuf = 0;
#pragma unroll 1
    for (int it = 0; it < NIT; it++) {
        asm volatile("cp.async.wait_group %0;" :: "n"(NSTAGE - 2) : "memory");
        __syncthreads();
        if (it + 2 < NIT) {
            int nb = cbuf + 2; if (nb >= NSTAGE) nb -= NSTAGE;
            stage_copy(it + 2, nb);
        }

        const uint32_t* sA = smem + cbuf * BUF2_WORDS;
        const uint32_t* sB = sA + AWORDS;

#pragma unroll
        for (int ks = 0; ks < 4; ks++) {
            const int sw0 = ((2 * ks)     ^ grp) * 4 + tg;
            const int sw1 = ((2 * ks + 1) ^ grp) * 4 + tg;
            uint32_t af[4][4];
#pragma unroll
            for (int mt = 0; mt < 4; mt++) {
                const int r0 = (wm + mt * 16 + grp) * 32;
                const int r1 = r0 + 8 * 32;
                af[mt][0] = sA[r0 + sw0];
                af[mt][1] = sA[r1 + sw0];
                af[mt][2] = sA[r0 + sw1];
                af[mt][3] = sA[r1 + sw1];
            }
            uint32_t bf[4][2];
#pragma unroll
            for (int nt = 0; nt < 4; nt++) {
                const int rb = (wn + nt * 8 + grp) * 32;
                bf[nt][0] = sB[rb + sw0];
                bf[nt][1] = sB[rb + sw1];
            }
#pragma unroll
            for (int mt = 0; mt < 4; mt++)
#pragma unroll
                for (int nt = 0; nt < 4; nt++)
                    mma_f16(acc[mt][nt][0], acc[mt][nt][1], acc[mt][nt][2], acc[mt][nt][3],
                            af[mt][0], af[mt][1], af[mt][2], af[mt][3],
                            bf[nt][0], bf[nt][1]);
        }
        cbuf++; if (cbuf >= NSTAGE) cbuf = 0;
    }

    // ---- epilogue ----
    if (MODE == 1) {
        __syncthreads();                      // smem reuse for staging
        __half* Ch = (__half*)Cv;
        const int ct = (int)((bn + wn) >> 5);
        __half2* es = reinterpret_cast<__half2*>(smem);   // stride 68 half2/row
#pragma unroll
        for (int mt = 0; mt < 4; mt++) {
            const int  lr0 = wm + mt * 16 + grp;
            const long r0  = bm + lr0;
            float rs0 = 0.0f, rs1 = 0.0f;
#pragma unroll
            for (int nt = 0; nt < 4; nt++) {
                const int lc2 = (wn + nt * 8 + 2 * tg) >> 1;
                const float e00 = __expf(acc[mt][nt][0] * alpha);
                const float e01 = __expf(acc[mt][nt][1] * alpha);
                const float e10 = __expf(acc[mt][nt][2] * alpha);
                const float e11 = __expf(acc[mt][nt][3] * alpha);
                const __half2 h0 = __floats2half2_rn(e00, e01);
                const __half2 h1 = __floats2half2_rn(e10, e11);
                const float2 b0 = __half22float2(h0);
                const float2 b1 = __half22float2(h1);
                rs0 += b0.x + b0.y;
                rs1 += b1.x + b1.y;
                es[lr0 * 68 + lc2]       = h0;
                es[(lr0 + 8) * 68 + lc2] = h1;
            }
            rs0 += __shfl_xor_sync(0xffffffffu, rs0, 1);
            rs0 += __shfl_xor_sync(0xffffffffu, rs0, 2);
            rs1 += __shfl_xor_sync(0xffffffffu, rs1, 1);
            rs1 += __shfl_xor_sync(0xffffffffu, rs1, 2);
            if (tg == 0) {
                aux[(size_t)r0 * PS + ct]       = rs0;
                aux[(size_t)(r0 + 8) * PS + ct] = rs1;
            }
        }
        __syncthreads();
#pragma unroll
        for (int i = 0; i < 8; i++) {         // 128 rows x 16 chunks of 16B
            const int idx = i * 256 + tid;
            const int row = idx >> 4;
            const int c4  = idx & 15;
            const uint4 d = *reinterpret_cast<const uint4*>(smem + row * 68 + c4 * 4);
            *reinterpret_cast<uint4*>(Ch + (bm + row) * (long)ldc + bn + c4 * 8) = d;
        }
    } else if (MODE == 3) {
        __half* Ch = (__half*)Cv;
#pragma unroll
        for (int mt = 0; mt < 4; mt++) {
            const long r0 = bm + wm + mt * 16 + grp;
#pragma unroll
            for (int nt = 0; nt < 4; nt++) {
                const int cn = (int)bn + wn + nt * 8 + 2 * tg;
                float v00 = acc[mt][nt][0] * alpha;
                float v01 = acc[mt][nt][1] * alpha;
                float v10 = acc[mt][nt][2] * alpha;
                float v11 = acc[mt][nt][3] * alpha;
                if (HASBIAS) {
                    const float b0 = bias[cn], b1 = bias[cn + 1];
                    v00 += b0; v01 += b1;
                    v10 += b0; v11 += b1;
                }
                Ch[(size_t)cn * ldc + r0]           = __float2half_rn(v00);
                Ch[(size_t)(cn + 1) * ldc + r0]     = __float2half_rn(v01);
                Ch[(size_t)cn * ldc + r0 + 8]       = __float2half_rn(v10);
                Ch[(size_t)(cn + 1) * ldc + r0 + 8] = __float2half_rn(v11);
            }
        }
    } else if (OUTHALF) {
        __syncthreads();
        __half* Ch = (__half*)Cv;
        __half2* es = reinterpret_cast<__half2*>(smem);   // stride 68
#pragma unroll
        for (int mt = 0; mt < 4; mt++) {
            const int lr0 = wm + mt * 16 + grp;
#pragma unroll
            for (int nt = 0; nt < 4; nt++) {
                const int cn  = (int)bn + wn + nt * 8 + 2 * tg;
                const int lc2 = (wn + nt * 8 + 2 * tg) >> 1;
                float v00 = acc[mt][nt][0] * alpha;
                float v01 = acc[mt][nt][1] * alpha;
                float v10 = acc[mt][nt][2] * alpha;
                float v11 = acc[mt][nt][3] * alpha;
                if (HASBIAS) {
                    const float b0 = bias[cn], b1 = bias[cn + 1];
                    v00 += b0; v01 += b1;
                    v10 += b0; v11 += b1;
                }
                es[lr0 * 68 + lc2]       = __floats2half2_rn(v00, v01);
                es[(lr0 + 8) * 68 + lc2] = __floats2half2_rn(v10, v11);
            }
        }
        __syncthreads();
#pragma unroll
        for (int i = 0; i < 8; i++) {
            const int idx = i * 256 + tid;
            const int row = idx >> 4;
            const int c4  = idx & 15;
            const uint4 d = *reinterpret_cast<const uint4*>(smem + row * 68 + c4 * 4);
            *reinterpret_cast<uint4*>(Ch + (bm + row) * (long)ldc + bn + c4 * 8) = d;
        }
    } else {
        __syncthreads();
        float* Cf = (float*)Cv;
        float* fs = reinterpret_cast<float*>(smem);        // stride 132 floats/row
#pragma unroll
        for (int mt = 0; mt < 4; mt++) {
            const int lr0 = wm + mt * 16 + grp;
#pragma unroll
            for (int nt = 0; nt < 4; nt++) {
                const int cn = (int)bn + wn + nt * 8 + 2 * tg;
                const int lc = wn + nt * 8 + 2 * tg;
                float v00 = acc[mt][nt][0] * alpha;
                float v01 = acc[mt][nt][1] * alpha;
                float v10 = acc[mt][nt][2] * alpha;
                float v11 = acc[mt][nt][3] * alpha;
                if (HASBIAS) {
                    const float b0 = bias[cn], b1 = bias[cn + 1];
                    v00 += b0; v01 += b1;
                    v10 += b0; v11 += b1;
                }
                *reinterpret_cast<float2*>(fs + lr0 * 132 + lc)       = make_float2(v00, v01);
                *reinterpret_cast<float2*>(fs + (lr0 + 8) * 132 + lc) = make_float2(v10, v11);
            }
        }
        __syncthreads();
#pragma unroll
        for (int i = 0; i < 16; i++) {        // 128 rows x 32 chunks of 16B
            const int idx = i * 256 + tid;
            const int row = idx >> 5;
            const int c4  = idx & 31;
            const float4 d = *reinterpret_cast<const float4*>(fs + row * 132 + c4 * 4);
            *reinterpret_cast<float4*>(Cf + (bm + row) * (long)ldc + bn + c4 * 4) = d;
        }
    }
}

// ---------------------------------------------------------------------------
// gemm_av2: CTA 64x256, warp tile 32x64, 32-K stages, 2 CTAs/SM.
// attn writeback in mainloop; HOp store smem-staged coalesced.
// ---------------------------------------------------------------------------
__device__ __forceinline__ void gemm_av2(const __half* __restrict__ A, int lda,
                                         const __half* __restrict__ B, int ldb,
                                         __half* __restrict__ C, int ldc,
                                         int K,
                                         float* __restrict__ aux,
                                         const float* __restrict__ invrow)
{
    extern __shared__ uint32_t smem[];
    const uint32_t sbase = smem_u32(smem);

    const int tid  = threadIdx.x;
    const int wid  = tid >> 5;
    const int lane = tid & 31;
    const int grp  = lane >> 2;
    const int tg   = lane & 3;
    const int wm   = (wid >> 2) * 32;
    const int wn   = (wid & 3) * 64;

    const long bm = (long)blockIdx.y * 64;
    A += bm * (long)lda;

    const int sm4 = tid >> 2;
    const int c4  = tid & 3;

    const float invs = invrow[bm + sm4];

    float acc[2][8][4];
#pragma unroll
    for (int i = 0; i < 2; i++)
#pragma unroll
        for (int j = 0; j < 8; j++)
#pragma unroll
            for (int r = 0; r < 4; r++) acc[i][j][r] = 0.0f;

    const int NIT = K >> 5;
    const int AWORDS = 64 * 16;

    auto stage_copy = [&](int stage, int buf) {
        const uint32_t db = sbase + (uint32_t)buf * (BUFA_WORDS * 4);
        const __half* Ak = A + stage * 32 + c4 * 8;
        const __half* Bk = B + stage * 32 + c4 * 8;
        {
            const int r = sm4;
            const int w = r * 16 + ((c4 * 4) ^ (((r >> 1) & 3) << 2));
            cp16(db + (uint32_t)w * 4, Ak + (long)r * lda);
        }
        const uint32_t dbB = db + (uint32_t)AWORDS * 4;
#pragma unroll
        for (int c = 0; c < 4; c++) {
            const int r = sm4 + c * 64;
            const int w = r * 16 + ((c4 * 4) ^ (((r >> 1) & 3) << 2));
            cp16(dbB + (uint32_t)w * 4, Bk + (long)r * ldb);
        }
        asm volatile("cp.async.commit_group;" ::: "memory");
    };

    stage_copy(0, 0);
    stage_copy(1, 1);

    int cbuf = 0;
#pragma unroll 1
    for (int it = 0; it < NIT; it++) {
        asm volatile("cp.async.wait_group %0;" :: "n"(NSTAGE - 2) : "memory");
        __syncthreads();
        if (it + 2 < NIT) {
            int nb = cbuf + 2; if (nb >= NSTAGE) nb -= NSTAGE;
            stage_copy(it + 2, nb);
        }

        const uint32_t* sA = smem + cbuf * BUFA_WORDS;
        const uint32_t* sB = sA + AWORDS;

        {   // normalized fp32 attn writeback (each E element staged once)
            const int m = sm4;
            const int w = m * 16 + ((c4 * 4) ^ (((m >> 1) & 3) << 2));
            const uint4 d = *reinterpret_cast<const uint4*>(sA + w);
            float2 f0 = __half22float2(*reinterpret_cast<const __half2*>(&d.x));
            float2 f1 = __half22float2(*reinterpret_cast<const __half2*>(&d.y));
            float2 f2 = __half22float2(*reinterpret_cast<const __half2*>(&d.z));
            float2 f3 = __half22float2(*reinterpret_cast<const __half2*>(&d.w));
            float4 o0 = make_float4(f0.x * invs, f0.y * invs, f1.x * invs, f1.y * invs);
            float4 o1 = make_float4(f2.x * invs, f2.y * invs, f3.x * invs, f3.y * invs);
            float* dst = aux + (bm + m) * (long)lda + it * 32 + c4 * 8;
            *reinterpret_cast<float4*>(dst)     = o0;
            *reinterpret_cast<float4*>(dst + 4) = o1;
        }

#pragma unroll
        for (int ks = 0; ks < 2; ks++) {
            const int kb = ks * 8;
            uint32_t af[2][4];
#pragma unroll
            for (int mt = 0; mt < 2; mt++) {
                const int r0 = wm + mt * 16 + grp;
                const int r1 = r0 + 8;
                const int s0 = ((r0 >> 1) & 3) << 2;
                const int s1 = ((r1 >> 1) & 3) << 2;
                af[mt][0] = sA[r0 * 16 + ((kb + tg)     ^ s0)];
                af[mt][1] = sA[r1 * 16 + ((kb + tg)     ^ s1)];
                af[mt][2] = sA[r0 * 16 + ((kb + tg + 4) ^ s0)];
                af[mt][3] = sA[r1 * 16 + ((kb + tg + 4) ^ s1)];
            }
            uint32_t bf[8][2];
#pragma unroll
            for (int nt = 0; nt < 8; nt++) {
                const int rb = wn + nt * 8 + grp;
                const int sb = ((rb >> 1) & 3) << 2;
                bf[nt][0] = sB[rb * 16 + ((kb + tg)     ^ sb)];
                bf[nt][1] = sB[rb * 16 + ((kb + tg + 4) ^ sb)];
            }
#pragma unroll
            for (int mt = 0; mt < 2; mt++)
#pragma unroll
                for (int nt = 0; nt < 8; nt++)
                    mma_f16(acc[mt][nt][0], acc[mt][nt][1], acc[mt][nt][2], acc[mt][nt][3],
                            af[mt][0], af[mt][1], af[mt][2], af[mt][3],
                            bf[nt][0], bf[nt][1]);
        }
        cbuf++; if (cbuf >= NSTAGE) cbuf = 0;
    }

    // epilogue: invrow-scaled fp16 HO partial, smem-staged (stride 132 half2)
    __syncthreads();
    __half2* es = reinterpret_cast<__half2*>(smem);
#pragma unroll
    for (int mt = 0; mt < 2; mt++) {
        const int  lr0 = wm + mt * 16 + grp;
        const long r0  = bm + lr0;
        const float s0 = invrow[r0];
        const float s1 = invrow[r0 + 8];
#pragma unroll
        for (int nt = 0; nt < 8; nt++) {
            const int lc2 = (wn + nt * 8 + 2 * tg) >> 1;
            es[lr0 * 132 + lc2]       = __floats2half2_rn(acc[mt][nt][0] * s0, acc[mt][nt][1] * s0);
            es[(lr0 + 8) * 132 + lc2] = __floats2half2_rn(acc[mt][nt][2] * s1, acc[mt][nt][3] * s1);
        }
    }
    __syncthreads();
#pragma unroll
    for (int i = 0; i < 8; i++) {             // 64 rows x 32 chunks of 16B
        const int idx = i * 256 + tid;
        const int row = idx >> 5;
        const int cc  = idx & 31;
        const uint4 d = *reinterpret_cast<const uint4*>(smem + row * 132 + cc * 4);
        *reinterpret_cast<uint4*>(C + (bm + row) * (long)ldc + cc * 8) = d;
    }
}

// ---------------------------------------------------------------------------
__global__ void __launch_bounds__(256) f2h_kernel(const float* __restrict__ q,
                                                  const float* __restrict__ k,
                                                  const float* __restrict__ v)
{
    const int z = blockIdx.y;
    const float* src = z == 0 ? q : z == 1 ? k : v;
    __half* dst = z == 0 ? g_qin : z == 1 ? g_kin : g_vin;
    const size_t i = (size_t)blockIdx.x * 256 + threadIdx.x;
    const float4 val = reinterpret_cast<const float4*>(src)[i];
    __half2 h0 = __floats2half2_rn(val.x, val.y);
    __half2 h1 = __floats2half2_rn(val.z, val.w);
    uint2 o;
    o.x = *reinterpret_cast<uint32_t*>(&h0);
    o.y = *reinterpret_cast<uint32_t*>(&h1);
    reinterpret_cast<uint2*>(dst)[i] = o;
}

__global__ void __launch_bounds__(256) transw_kernel(
    const float* __restrict__ Wq, const float* __restrict__ Wk,
    const float* __restrict__ Wv, const float* __restrict__ Wo)
{
    __shared__ float t[32][33];
    const int z = blockIdx.z;
    const float* src;
    __half* dst;
    int R, C;
    if (z == 12) { src = Wo; dst = g_WoTh; R = DM; C = DM; }
    else {
        const int mat = z >> 2, head = z & 3;
        const float* W = mat == 0 ? Wq : mat == 1 ? Wk : Wv;
        src = W + (size_t)head * DM * DK;
        dst = g_WTh + (size_t)z * DK * DM;
        R = DM; C = DK;
        if (blockIdx.x >= 8) return;
    }

    const int c0 = blockIdx.x * 32, r0 = blockIdx.y * 32;
    const int tx = threadIdx.x & 31, ty = threadIdx.x >> 5;
#pragma unroll
    for (int i = 0; i < 4; i++)
        t[ty + i * 8][tx] = src[(size_t)(r0 + ty + i * 8) * C + c0 + tx];
    __syncthreads();
#pragma unroll
    for (int i = 0; i < 4; i++)
        dst[(size_t)(c0 + ty + i * 8) * R + r0 + tx] = __float2half_rn(t[tx][ty + i * 8]);
}

__global__ void __launch_bounds__(256) invsum_kernel()
{
    const int row  = blockIdx.x * 8 + (threadIdx.x >> 5);
    const int lane = threadIdx.x & 31;
    const float* p = g_psum + (size_t)row * PS;
    float s = p[lane] + p[lane + 32] + p[lane + 64] + p[lane + 96];
#pragma unroll
    for (int o = 16; o > 0; o >>= 1) s += __shfl_xor_sync(0xffffffffu, s, o);
    if (lane == 0) g_invsum[row] = 1.0f / s;
}

__global__ void __launch_bounds__(256) hored_kernel()
{
    const size_t n2 = (size_t)BS_TOT * DM / 2;
    const size_t i  = (size_t)blockIdx.x * 256 + threadIdx.x;
    const __half2* p = reinterpret_cast<const __half2*>(g_HOp);
    float2 s = __half22float2(p[i]);
    float2 a1 = __half22float2(p[i + n2]);
    float2 a2 = __half22float2(p[i + 2 * n2]);
    float2 a3 = __half22float2(p[i + 3 * n2]);
    s.x += a1.x + a2.x + a3.x;
    s.y += a1.y + a2.y + a3.y;
    reinterpret_cast<__half2*>(g_HOh)[i] = __floats2half2_rn(s.x, s.y);
}

// ---------------------------------------------------------------------------
__global__ void __launch_bounds__(256, 2) proj_tc(
    const float* __restrict__ bq, const float* __restrict__ bk, const float* __restrict__ bv)
{
    const int z = blockIdx.z, mat = z >> 2, head = z & 3;
    const __half* A    = mat == 0 ? g_qin : mat == 1 ? g_kin : g_vin;
    const __half* B    = g_WTh + (size_t)z * DK * DM;
    const float*  bias = (mat == 0 ? bq : mat == 1 ? bk : bv) + head * DK;
    if (mat == 2) {
        __half* C = g_VTh + (size_t)head * BS_TOT * DK;
        const long b = (long)blockIdx.y / 32;
        __half* Cb = C + b * SEQ * DK - b * SEQ;
        gemm_h2<true, true, 3>(A, DM, B, DM, Cb, SEQ, DM, 1.0f, bias, nullptr);
    } else {
        __half* C = (mat == 0 ? g_Qh : g_Kh) + (size_t)head * BS_TOT * DK;
        gemm_h2<true, true, 0>(A, DM, B, DM, C, DK, DM, 1.0f, bias, nullptr);
    }
}

__global__ void __launch_bounds__(256, 2) scores_tc()
{
    const int z = blockIdx.z;
    gemm_h2<false, true, 1>(g_Qh + (size_t)z * SEQ * DK, DK,
                            g_Kh + (size_t)z * SEQ * DK, DK,
                            g_Eh + (size_t)z * SEQ * SEQ, SEQ, DK, 0.0625f,
                            nullptr, g_psum + (size_t)z * SEQ * PS);
}

__global__ void __launch_bounds__(256, 2) av_tc(float* __restrict__ attn_out)
{
    float* attn = attn_out ? attn_out : g_attn_fallback;
    const int z = blockIdx.z, h = z >> 1, b = z & 1;
    const int slab = blockIdx.x;
    const __half* A = g_Eh + (size_t)z * SEQ * SEQ + (size_t)slab * KSLAB;
    const __half* B = g_VTh + (size_t)z * DK * SEQ + (size_t)slab * KSLAB;
    __half* C = g_HOp + (size_t)slab * BS_TOT * DM + (size_t)b * SEQ * DM + h * DK;
    float* aux = attn + (size_t)z * SEQ * SEQ + (size_t)slab * KSLAB;
    gemm_av2(A, SEQ, B, SEQ, C, DM, KSLAB, aux, g_invsum + (size_t)z * SEQ);
}

__global__ void __launch_bounds__(256, 2) outproj_tc(const float* __restrict__ bo,
                                                     float* __restrict__ out)
{
    gemm_h2<true, false, 0>(g_HOh, DM, g_WoTh, DM, out, DM, DM, 1.0f, bo, nullptr);
}

// ---------------------------------------------------------------------------
extern "C" void kernel_launch(void* const* d_in, const int* in_sizes, int n_in,
                              void* d_out, int out_size)
{
    const float* q  = (const float*)d_in[0];
    const float* k  = (const float*)d_in[1];
    const float* v  = (const float*)d_in[2];
    const float* Wq = (const float*)d_in[3];
    const float* bq = (const float*)d_in[4];
    const float* Wk = (const float*)d_in[5];
    const float* bk = (const float*)d_in[6];
    const float* Wv = (const float*)d_in[7];
    const float* bv = (const float*)d_in[8];
    const float* Wo = (const float*)d_in[9];
    const float* bo = (const float*)d_in[10];

    float* out = (float*)d_out;
    const long OUT_ELEMS  = (long)NB * SEQ * DM;
    const long ATTN_ELEMS = (long)NH * NB * SEQ * SEQ;
    float* attn_out = nullptr;
    if ((long)out_size >= OUT_ELEMS + ATTN_ELEMS) attn_out = out + OUT_ELEMS;

    cudaFuncSetAttribute(proj_tc,    cudaFuncAttributeMaxDynamicSharedMemorySize, SMEM2_BYTES);
    cudaFuncSetAttribute(scores_tc,  cudaFuncAttributeMaxDynamicSharedMemorySize, SMEM2_BYTES);
    cudaFuncSetAttribute(av_tc,      cudaFuncAttributeMaxDynamicSharedMemorySize, SMEMA_BYTES);
    cudaFuncSetAttribute(outproj_tc, cudaFuncAttributeMaxDynamicSharedMemorySize, SMEM2_BYTES);

    f2h_kernel<<<dim3(BS_TOT * DM / 4 / 256, 3), 256>>>(q, k, v);

    transw_kernel<<<dim3(32, 32, 13), 256>>>(Wq, Wk, Wv, Wo);

    proj_tc<<<dim3(2, 64, 12), 256, SMEM2_BYTES>>>(bq, bk, bv);

    scores_tc<<<dim3(32, 32, 8), 256, SMEM2_BYTES>>>();

    invsum_kernel<<<dim3(NROWS / 8), 256>>>();

    av_tc<<<dim3(KSLABS, 64, 8), 256, SMEMA_BYTES>>>(attn_out);

    hored_kernel<<<dim3(BS_TOT * DM / 2 / 256), 256>>>();

    outproj_tc<<<dim3(8, 64, 1), 256, SMEM2_BYTES>>>(bo, out);
}